// round 12
// baseline (speedup 1.0000x reference)
#include <cuda_runtime.h>
#include <cuda_bf16.h>
#include <cuda_fp16.h>
#include <math.h>

#define NN 100000
#define EE 1600000
#define F_IN 1433
#define DD 64
#define DEPTH 3
#define ALPHA 0.9f
#define KC_EMB 90   // ceil(1433/16)

// ---------------- scratch (static device globals) ----------------
__device__ float    g_x0[NN * DD];
__device__ float    g_x [NN * DD];
__device__ float    g_agg[NN * DD];
__device__ float    g_q [NN * DD];
__device__ unsigned g_k2[NN * 32];   // half2-packed k rows (32 x half2 = 64 cols)
__device__ unsigned g_v2[NN * 32];   // half2-packed v rows
__device__ int      g_deg[NN];
__device__ int      g_off[NN + 1];
__device__ int      g_pos[NN];
__device__ int      g_csr[EE];
__device__ uint4    g_Bemb[KC_EMB * 256];  // packed split-bf16 emb weight
__device__ uint4    g_Bw[12 * 1024];       // q,k,v,o x 3 layers (K=64 -> KC=4)

// ---------------- helpers ----------------
__device__ __forceinline__ void split2(float x, float y, unsigned& hi, unsigned& lo) {
    __nv_bfloat162 h = __floats2bfloat162_rn(x, y);
    float rx = x - __low2float(h);
    float ry = y - __high2float(h);
    __nv_bfloat162 l = __floats2bfloat162_rn(rx, ry);
    hi = *reinterpret_cast<unsigned*>(&h);
    lo = *reinterpret_cast<unsigned*>(&l);
}

__device__ __forceinline__ void mma16816(float* c, const unsigned* a,
                                         unsigned b0, unsigned b1) {
    asm volatile(
        "mma.sync.aligned.m16n8k16.row.col.f32.bf16.bf16.f32 "
        "{%0,%1,%2,%3},{%4,%5,%6,%7},{%8,%9},{%0,%1,%2,%3};\n"
        : "+f"(c[0]), "+f"(c[1]), "+f"(c[2]), "+f"(c[3])
        : "r"(a[0]), "r"(a[1]), "r"(a[2]), "r"(a[3]), "r"(b0), "r"(b1));
}

__device__ __forceinline__ float2 h2f2(unsigned w) {
    return __half22float2(*reinterpret_cast<__half2*>(&w));
}

// ---------------- B packing ----------------
__global__ void pack_b_kernel(const float* __restrict__ B, uint4* __restrict__ out,
                              int K, int KC) {
    int idx = blockIdx.x * blockDim.x + threadIdx.x;
    if (idx >= KC * 256) return;
    int lane = idx & 31, nt = (idx >> 5) & 7, kc = idx >> 8;
    int col = nt * 8 + (lane >> 2);
    int kr = kc * 16 + (lane & 3) * 2;
    float f0 = (kr     < K) ? B[(kr    ) * 64 + col] : 0.f;
    float f1 = (kr + 1 < K) ? B[(kr + 1) * 64 + col] : 0.f;
    float f2 = (kr + 8 < K) ? B[(kr + 8) * 64 + col] : 0.f;
    float f3 = (kr + 9 < K) ? B[(kr + 9) * 64 + col] : 0.f;
    unsigned h0, l0, h1, l1;
    split2(f0, f1, h0, l0);
    split2(f2, f3, h1, l1);
    out[idx] = make_uint4(h0, h1, l0, l1);
}

__global__ void pack_w_kernel(const float* __restrict__ Wq, const float* __restrict__ Wk,
                              const float* __restrict__ Wv, const float* __restrict__ Wo,
                              uint4* __restrict__ out) {
    int idx = blockIdx.x * blockDim.x + threadIdx.x;
    if (idx >= 12 * 1024) return;
    int m = idx >> 10;
    int l = m >> 2, w = m & 3;
    const float* B = (w == 0 ? Wq : w == 1 ? Wk : w == 2 ? Wv : Wo) + l * 4096;
    int rest = idx & 1023;
    int lane = rest & 31, nt = (rest >> 5) & 7, kc = rest >> 8;
    int col = nt * 8 + (lane >> 2);
    int kr = kc * 16 + (lane & 3) * 2;
    float f0 = B[(kr    ) * 64 + col];
    float f1 = B[(kr + 1) * 64 + col];
    float f2 = B[(kr + 8) * 64 + col];
    float f3 = B[(kr + 9) * 64 + col];
    unsigned h0, l0, h1, l1;
    split2(f0, f1, h0, l0);
    split2(f2, f3, h1, l1);
    out[idx] = make_uint4(h0, h1, l0, l1);
}

// ------- fused GEMM: main GEMM + (bias|gate) + LN + in-register QKV GEMMs --
// 2-deep register prefetch: stage st+2's LDGs issue during stage st's MMAs.
template <int EPI>
__global__ __launch_bounds__(128)
void gemm_fused_kernel(const float* __restrict__ A, const uint4* __restrict__ Bp,
                       float* __restrict__ O0,
                       const float* __restrict__ bias_gw,
                       const float* __restrict__ gb,
                       const float* __restrict__ res,
                       const float* __restrict__ x0p,
                       const float* __restrict__ lns,
                       const float* __restrict__ lnb,
                       const uint4* __restrict__ Bqkv,
                       float* __restrict__ Oq,
                       int M, int K, int KC) {
    __shared__ float sA[64 * 32];
    const int tid = threadIdx.x, warp = tid >> 5, lane = tid & 31;
    const int rowBase = blockIdx.x * 64;
    const int nStages = (KC + 1) >> 1;

    float acc[8][4];
#pragma unroll
    for (int nt = 0; nt < 8; ++nt)
#pragma unroll
        for (int j = 0; j < 4; ++j) acc[nt][j] = 0.f;

    const int cr0 = warp * 16 + (lane >> 2);
    const int cr1 = cr0 + 8;
    const int sw0 = (cr0 & 3) << 3;
    const int sw1 = (cr1 & 3) << 3;

    float rbufA[16], rbufB[16];

#define LOADSTAGE(ST, RB)                                                      \
    do {                                                                       \
        int cBase = (ST) * 32;                                                 \
        int gc = cBase + lane;                                                 \
        bool cok = gc < K;                                                     \
        _Pragma("unroll")                                                      \
        for (int i = 0; i < 16; ++i) {                                         \
            int gr = rowBase + i * 4 + warp;                                   \
            RB[i] = (gr < M && cok) ? __ldg(A + (long)gr * K + gc) : 0.f;      \
        }                                                                      \
    } while (0)

    LOADSTAGE(0, rbufA);
    if (nStages > 1) LOADSTAGE(1, rbufB);
    for (int st = 0; st < nStages; ++st) {
        float* rb = (st & 1) ? rbufB : rbufA;
#pragma unroll
        for (int i = 0; i < 16; ++i) {
            int rr = i * 4 + warp;
            sA[rr * 32 + (lane ^ ((rr & 3) << 3))] = rb[i];
        }
        __syncthreads();
        if (st + 2 < nStages) LOADSTAGE(st + 2, rb);
#pragma unroll
        for (int half = 0; half < 2; ++half) {
            int kc = st * 2 + half;
            if (kc < KC) {
                int c0 = half * 16 + (lane & 3) * 2;
                float2 fA = *(const float2*)&sA[cr0 * 32 + ((c0    ) ^ sw0)];
                float2 fB = *(const float2*)&sA[cr1 * 32 + ((c0    ) ^ sw1)];
                float2 fC = *(const float2*)&sA[cr0 * 32 + ((c0 + 8) ^ sw0)];
                float2 fD = *(const float2*)&sA[cr1 * 32 + ((c0 + 8) ^ sw1)];
                unsigned ahi[4], alo[4];
                split2(fA.x, fA.y, ahi[0], alo[0]);
                split2(fB.x, fB.y, ahi[1], alo[1]);
                split2(fC.x, fC.y, ahi[2], alo[2]);
                split2(fD.x, fD.y, ahi[3], alo[3]);
                const uint4* bp = Bp + (size_t)kc * 256 + lane;
#pragma unroll
                for (int nt = 0; nt < 8; ++nt) {
                    uint4 b = __ldg(&bp[nt * 32]);
                    mma16816(acc[nt], ahi, b.x, b.y);
                    mma16816(acc[nt], alo, b.x, b.y);
                    mma16816(acc[nt], ahi, b.z, b.w);
                }
            }
        }
        __syncthreads();
    }
#undef LOADSTAGE

    const int cbase = (lane & 3) * 2;
    const int gr[2] = { rowBase + cr0, rowBase + cr1 };
    float hv[2][8][2];          // row values in A-fragment layout
    float sum[2] = {0.f, 0.f}, sq[2] = {0.f, 0.f};

    if (EPI == 1) {
        // embedding: bias add, store x0, LN -> hv
#pragma unroll
        for (int f = 0; f < 2; ++f)
#pragma unroll
            for (int nt = 0; nt < 8; ++nt) {
                int cc = nt * 8 + cbase;
                float a0 = acc[nt][2 * f]     + bias_gw[cc];
                float a1 = acc[nt][2 * f + 1] + bias_gw[cc + 1];
                hv[f][nt][0] = a0; hv[f][nt][1] = a1;
                sum[f] += a0 + a1;
                sq[f]  += a0 * a0 + a1 * a1;
                if (gr[f] < M)
                    *(float2*)(O0 + (long)gr[f] * 64 + cc) = make_float2(a0, a1);
            }
    } else {
        // EPI 2: gated residual + alpha mix
        const float* gw = bias_gw;
        float rr[2][8][2], zz[2][8][2];
        float s[2] = {0.f, 0.f};
#pragma unroll
        for (int f = 0; f < 2; ++f) {
            bool ok = gr[f] < M;
#pragma unroll
            for (int nt = 0; nt < 8; ++nt) {
                int cc = nt * 8 + cbase;
                float2 rv = ok ? *(const float2*)(res + (long)gr[f] * 64 + cc)
                               : make_float2(0.f, 0.f);
                float2 zv = ok ? *(const float2*)(x0p + (long)gr[f] * 64 + cc)
                               : make_float2(0.f, 0.f);
                rr[f][nt][0] = rv.x; rr[f][nt][1] = rv.y;
                zz[f][nt][0] = zv.x; zz[f][nt][1] = zv.y;
                float o0 = acc[nt][2 * f], o1 = acc[nt][2 * f + 1];
                s[f] += o0 * gw[cc]        + o1 * gw[cc + 1]
                      + rv.x * gw[64 + cc] + rv.y * gw[65 + cc]
                      + (o0 - rv.x) * gw[128 + cc] + (o1 - rv.y) * gw[129 + cc];
            }
        }
#pragma unroll
        for (int o = 1; o <= 2; o <<= 1) {
            s[0] += __shfl_xor_sync(~0u, s[0], o);
            s[1] += __shfl_xor_sync(~0u, s[1], o);
        }
#pragma unroll
        for (int f = 0; f < 2; ++f) {
            float g = 1.f / (1.f + __expf(-(s[f] + gb[0])));
#pragma unroll
            for (int nt = 0; nt < 8; ++nt) {
                float o0 = acc[nt][2 * f], o1 = acc[nt][2 * f + 1];
                float n0 = ALPHA * (g * o0 + (1.f - g) * rr[f][nt][0])
                         + (1.f - ALPHA) * zz[f][nt][0];
                float n1 = ALPHA * (g * o1 + (1.f - g) * rr[f][nt][1])
                         + (1.f - ALPHA) * zz[f][nt][1];
                hv[f][nt][0] = n0; hv[f][nt][1] = n1;
                sum[f] += n0 + n1;
                sq[f]  += n0 * n0 + n1 * n1;
                if (gr[f] < M) {
                    int cc = nt * 8 + cbase;
                    *(float2*)(O0 + (long)gr[f] * 64 + cc) = make_float2(n0, n1);
                }
            }
        }
    }

    if (lns) {
        // LayerNorm in registers (quad reduction over the 4 lanes of a row)
#pragma unroll
        for (int o = 1; o <= 2; o <<= 1) {
            sum[0] += __shfl_xor_sync(~0u, sum[0], o);
            sum[1] += __shfl_xor_sync(~0u, sum[1], o);
            sq[0]  += __shfl_xor_sync(~0u, sq[0],  o);
            sq[1]  += __shfl_xor_sync(~0u, sq[1],  o);
        }
#pragma unroll
        for (int f = 0; f < 2; ++f) {
            float mu = sum[f] * (1.f / 64.f);
            float var = sq[f] * (1.f / 64.f) - mu * mu;
            float rstd = rsqrtf(var + 1e-5f);
#pragma unroll
            for (int nt = 0; nt < 8; ++nt) {
                int cc = nt * 8 + cbase;
                hv[f][nt][0] = (hv[f][nt][0] - mu) * rstd * lns[cc]     + lnb[cc];
                hv[f][nt][1] = (hv[f][nt][1] - mu) * rstd * lns[cc + 1] + lnb[cc + 1];
            }
        }
    }

    if (Bqkv) {
        // in-register QKV GEMMs: hv already sits in mma A-fragment layout
#pragma unroll
        for (int m = 0; m < 3; ++m) {
            float a2[8][4];
#pragma unroll
            for (int nt = 0; nt < 8; ++nt)
#pragma unroll
                for (int j = 0; j < 4; ++j) a2[nt][j] = 0.f;
#pragma unroll
            for (int kc = 0; kc < 4; ++kc) {
                unsigned ahi[4], alo[4];
                split2(hv[0][2*kc][0],   hv[0][2*kc][1],   ahi[0], alo[0]);
                split2(hv[1][2*kc][0],   hv[1][2*kc][1],   ahi[1], alo[1]);
                split2(hv[0][2*kc+1][0], hv[0][2*kc+1][1], ahi[2], alo[2]);
                split2(hv[1][2*kc+1][0], hv[1][2*kc+1][1], ahi[3], alo[3]);
                const uint4* bm = Bqkv + (size_t)m * 1024 + kc * 256 + lane;
#pragma unroll
                for (int nt = 0; nt < 8; ++nt) {
                    uint4 b = __ldg(&bm[nt * 32]);
                    mma16816(a2[nt], ahi, b.x, b.y);
                    mma16816(a2[nt], alo, b.x, b.y);
                    mma16816(a2[nt], ahi, b.z, b.w);
                }
            }
            if (m == 0) {
                // q in fp32
#pragma unroll
                for (int f = 0; f < 2; ++f) {
                    if (gr[f] >= M) continue;
#pragma unroll
                    for (int nt = 0; nt < 8; ++nt) {
                        int cc = nt * 8 + cbase;
                        *(float2*)(Oq + (long)gr[f] * 64 + cc) =
                            make_float2(a2[nt][2 * f], a2[nt][2 * f + 1]);
                    }
                }
            } else {
                // k/v packed half2
                unsigned* O2 = (m == 1) ? g_k2 : g_v2;
#pragma unroll
                for (int f = 0; f < 2; ++f) {
                    if (gr[f] >= M) continue;
#pragma unroll
                    for (int nt = 0; nt < 8; ++nt) {
                        __half2 hh = __floats2half2_rn(a2[nt][2 * f],
                                                       a2[nt][2 * f + 1]);
                        O2[(long)gr[f] * 32 + nt * 4 + (lane & 3)] =
                            *reinterpret_cast<unsigned*>(&hh);
                    }
                }
            }
        }
    }
}

// ---------------- CSR construction ----------------
__global__ void zero_deg_kernel() {
    int i = blockIdx.x * blockDim.x + threadIdx.x;
    if (i < NN) g_deg[i] = 0;
}

__global__ void hist_kernel(const int* __restrict__ ei) {
    int e = blockIdx.x * blockDim.x + threadIdx.x;
    if (e < EE) atomicAdd(&g_deg[ei[EE + e]], 1);
}

__global__ void scan_kernel() {
    __shared__ int ssum[1024];
    const int t = threadIdx.x;
    const int CHUNK = (NN + 1023) / 1024;
    int beg = t * CHUNK;
    int end = beg + CHUNK; if (end > NN) end = NN;
    int s = 0;
    for (int i = beg; i < end; ++i) s += g_deg[i];
    ssum[t] = s;
    __syncthreads();
    for (int d = 1; d < 1024; d <<= 1) {
        int v = (t >= d) ? ssum[t - d] : 0;
        __syncthreads();
        ssum[t] += v;
        __syncthreads();
    }
    int run = (t == 0) ? 0 : ssum[t - 1];
    for (int i = beg; i < end; ++i) {
        g_off[i] = run;
        g_pos[i] = run;
        run += g_deg[i];
    }
    if (t == 1023) g_off[NN] = ssum[1023];
}

__global__ void fill_kernel(const int* __restrict__ ei) {
    int e = blockIdx.x * blockDim.x + threadIdx.x;
    if (e < EE) {
        int d = ei[EE + e];
        int p = atomicAdd(&g_pos[d], 1);
        g_csr[p] = ei[e];
    }
}

// ---------------- fused edge attention: warp per dst, half2 k/v ------------
__global__ __launch_bounds__(256)
void attn_kernel() {
    int warp = (blockIdx.x * blockDim.x + threadIdx.x) >> 5;
    int lane = threadIdx.x & 31;
    if (warp >= NN) return;
    float2 qv = ((const float2*)(g_q + (size_t)warp * 64))[lane];
    qv.x *= 0.25f; qv.y *= 0.25f;      // fold DH^-0.5
    float l = 0.f, lB = 0.f;
    float ax = 0.f, ay = 0.f, bx = 0.f, by = 0.f;
    int beg = g_off[warp], end = g_off[warp + 1];
    int e = beg;
    for (; e + 1 < end; e += 2) {
        int s0 = g_csr[e], s1 = g_csr[e + 1];
        unsigned kw0 = g_k2[(size_t)s0 * 32 + lane];
        unsigned vw0 = g_v2[(size_t)s0 * 32 + lane];
        unsigned kw1 = g_k2[(size_t)s1 * 32 + lane];
        unsigned vw1 = g_v2[(size_t)s1 * 32 + lane];
        float2 k0 = h2f2(kw0), v0 = h2f2(vw0);
        float2 k1 = h2f2(kw1), v1 = h2f2(vw1);
        float d0 = qv.x * k0.x + qv.y * k0.y;
        float d1 = qv.x * k1.x + qv.y * k1.y;
#pragma unroll
        for (int o = 4; o; o >>= 1) {
            d0 += __shfl_xor_sync(~0u, d0, o);
            d1 += __shfl_xor_sync(~0u, d1, o);
        }
        float p0 = __expf(d0), p1 = __expf(d1);
        l  += p0;  ax += p0 * v0.x;  ay += p0 * v0.y;
        lB += p1;  bx += p1 * v1.x;  by += p1 * v1.y;
    }
    if (e < end) {
        int s0 = g_csr[e];
        unsigned kw0 = g_k2[(size_t)s0 * 32 + lane];
        unsigned vw0 = g_v2[(size_t)s0 * 32 + lane];
        float2 k0 = h2f2(kw0), v0 = h2f2(vw0);
        float d0 = qv.x * k0.x + qv.y * k0.y;
#pragma unroll
        for (int o = 4; o; o >>= 1) d0 += __shfl_xor_sync(~0u, d0, o);
        float p0 = __expf(d0);
        l += p0; ax += p0 * v0.x; ay += p0 * v0.y;
    }
    l += lB; ax += bx; ay += by;
    float inv = 1.f / (l + 1e-9f);
    ((float2*)(g_agg + (size_t)warp * 64))[lane] = make_float2(ax * inv, ay * inv);
}

// ---------------- launch ----------------
extern "C" void kernel_launch(void* const* d_in, const int* in_sizes, int n_in,
                              void* d_out, int out_size) {
    const float* nodes = (const float*)d_in[0];
    const int*   ei    = (const int*)  d_in[1];
    const float* emb_W = (const float*)d_in[2];
    const float* emb_b = (const float*)d_in[3];
    const float* ln_s  = (const float*)d_in[4];
    const float* ln_b  = (const float*)d_in[5];
    const float* Wq    = (const float*)d_in[6];
    const float* Wk    = (const float*)d_in[7];
    const float* Wv    = (const float*)d_in[8];
    const float* Wo    = (const float*)d_in[9];
    const float* gW    = (const float*)d_in[10];
    const float* gb    = (const float*)d_in[11];
    float* out = (float*)d_out;

    float *px0, *px, *pagg, *pq;
    uint4 *pBemb, *pBw;
    cudaGetSymbolAddress((void**)&px0,  g_x0);
    cudaGetSymbolAddress((void**)&px,   g_x);
    cudaGetSymbolAddress((void**)&pagg, g_agg);
    cudaGetSymbolAddress((void**)&pq,   g_q);
    cudaGetSymbolAddress((void**)&pBemb, g_Bemb);
    cudaGetSymbolAddress((void**)&pBw,   g_Bw);

    const int gemmGrid = (NN + 63) / 64;     // 1563
    const int warpGrid = (NN + 7) / 8;

    // launches 1-3
    pack_b_kernel<<<(KC_EMB * 256 + 255) / 256, 256>>>(emb_W, pBemb, F_IN, KC_EMB);
    pack_w_kernel<<<(12 * 1024 + 255) / 256, 256>>>(Wq, Wk, Wv, Wo, pBw);
    zero_deg_kernel<<<(NN + 255) / 256, 256>>>();
    // launch 4 (ncu capture): embedding GEMM + bias + LN0 + QKV0, all fused
    gemm_fused_kernel<1><<<gemmGrid, 128>>>(
        nodes, pBemb, px0, emb_b, nullptr, nullptr, nullptr,
        ln_s, ln_b, pBw, pq, NN, F_IN, KC_EMB);
    // CSR build
    hist_kernel<<<(EE + 255) / 256, 256>>>(ei);
    scan_kernel<<<1, 1024>>>();
    fill_kernel<<<(EE + 255) / 256, 256>>>(ei);

    for (int l = 0; l < DEPTH; ++l) {
        attn_kernel<<<warpGrid, 256>>>();   // q,k,v -> agg
        const float* res = (l == 0) ? px0 : px;
        float* dst = (l == DEPTH - 1) ? out : px;
        const float* nls = (l == DEPTH - 1) ? nullptr : ln_s + (l + 1) * 64;
        const float* nlb = (l == DEPTH - 1) ? nullptr : ln_b + (l + 1) * 64;
        const uint4* bqkv = (l == DEPTH - 1) ? nullptr
                                             : pBw + (size_t)(l + 1) * 4 * 1024;
        // Wo GEMM + gate + alpha mix + next LN + next QKV, all fused
        gemm_fused_kernel<2><<<gemmGrid, 128>>>(
            pagg, pBw + (size_t)(l * 4 + 3) * 1024, dst,
            gW + l * 192, gb + l, res, px0, nls, nlb,
            bqkv, pq, NN, 64, 4);
    }
}

// round 13
// speedup vs baseline: 1.0252x; 1.0252x over previous
#include <cuda_runtime.h>
#include <cuda_bf16.h>
#include <cuda_fp16.h>
#include <math.h>

#define NN 100000
#define EE 1600000
#define F_IN 1433
#define DD 64
#define DEPTH 3
#define ALPHA 0.9f
#define KC_EMB 90   // ceil(1433/16)

// ---------------- scratch (static device globals) ----------------
__device__ float    g_x0[NN * DD];
__device__ float    g_x [NN * DD];
__device__ float    g_agg[NN * DD];
__device__ float    g_q [NN * DD];
__device__ unsigned g_k2[NN * 32];   // half2-packed k rows
__device__ unsigned g_v2[NN * 32];   // half2-packed v rows
__device__ int      g_deg[NN];
__device__ int      g_off[NN + 1];
__device__ int      g_pos[NN];
__device__ int      g_csr[EE];
__device__ uint4    g_Bemb[KC_EMB * 256];  // packed split-bf16 emb weight
__device__ uint4    g_Bw[12 * 1024];       // q,k,v,o x 3 layers (K=64 -> KC=4)

// ---------------- helpers ----------------
__device__ __forceinline__ void split2(float x, float y, unsigned& hi, unsigned& lo) {
    __nv_bfloat162 h = __floats2bfloat162_rn(x, y);
    float rx = x - __low2float(h);
    float ry = y - __high2float(h);
    __nv_bfloat162 l = __floats2bfloat162_rn(rx, ry);
    hi = *reinterpret_cast<unsigned*>(&h);
    lo = *reinterpret_cast<unsigned*>(&l);
}

__device__ __forceinline__ void mma16816(float* c, const unsigned* a,
                                         unsigned b0, unsigned b1) {
    asm volatile(
        "mma.sync.aligned.m16n8k16.row.col.f32.bf16.bf16.f32 "
        "{%0,%1,%2,%3},{%4,%5,%6,%7},{%8,%9},{%0,%1,%2,%3};\n"
        : "+f"(c[0]), "+f"(c[1]), "+f"(c[2]), "+f"(c[3])
        : "r"(a[0]), "r"(a[1]), "r"(a[2]), "r"(a[3]), "r"(b0), "r"(b1));
}

__device__ __forceinline__ float2 h2f2(unsigned w) {
    return __half22float2(*reinterpret_cast<__half2*>(&w));
}

// ---------------- B packing ----------------
__global__ void pack_b_kernel(const float* __restrict__ B, uint4* __restrict__ out,
                              int K, int KC) {
    int idx = blockIdx.x * blockDim.x + threadIdx.x;
    if (idx >= KC * 256) return;
    int lane = idx & 31, nt = (idx >> 5) & 7, kc = idx >> 8;
    int col = nt * 8 + (lane >> 2);
    int kr = kc * 16 + (lane & 3) * 2;
    float f0 = (kr     < K) ? B[(kr    ) * 64 + col] : 0.f;
    float f1 = (kr + 1 < K) ? B[(kr + 1) * 64 + col] : 0.f;
    float f2 = (kr + 8 < K) ? B[(kr + 8) * 64 + col] : 0.f;
    float f3 = (kr + 9 < K) ? B[(kr + 9) * 64 + col] : 0.f;
    unsigned h0, l0, h1, l1;
    split2(f0, f1, h0, l0);
    split2(f2, f3, h1, l1);
    out[idx] = make_uint4(h0, h1, l0, l1);
}

__global__ void pack_w_kernel(const float* __restrict__ Wq, const float* __restrict__ Wk,
                              const float* __restrict__ Wv, const float* __restrict__ Wo,
                              uint4* __restrict__ out) {
    int idx = blockIdx.x * blockDim.x + threadIdx.x;
    if (idx >= 12 * 1024) return;
    int m = idx >> 10;
    int l = m >> 2, w = m & 3;
    const float* B = (w == 0 ? Wq : w == 1 ? Wk : w == 2 ? Wv : Wo) + l * 4096;
    int rest = idx & 1023;
    int lane = rest & 31, nt = (rest >> 5) & 7, kc = rest >> 8;
    int col = nt * 8 + (lane >> 2);
    int kr = kc * 16 + (lane & 3) * 2;
    float f0 = B[(kr    ) * 64 + col];
    float f1 = B[(kr + 1) * 64 + col];
    float f2 = B[(kr + 8) * 64 + col];
    float f3 = B[(kr + 9) * 64 + col];
    unsigned h0, l0, h1, l1;
    split2(f0, f1, h0, l0);
    split2(f2, f3, h1, l1);
    out[idx] = make_uint4(h0, h1, l0, l1);
}

// ------- fused GEMM: main GEMM + (bias|gate) + LN + in-register QKV GEMMs --
// 2-deep register prefetch with STATIC double buffers (manual 2x unroll).
template <int EPI>
__global__ __launch_bounds__(128)
void gemm_fused_kernel(const float* __restrict__ A, const uint4* __restrict__ Bp,
                       float* __restrict__ O0,
                       const float* __restrict__ bias_gw,
                       const float* __restrict__ gb,
                       const float* __restrict__ res,
                       const float* __restrict__ x0p,
                       const float* __restrict__ lns,
                       const float* __restrict__ lnb,
                       const uint4* __restrict__ Bqkv,
                       float* __restrict__ Oq,
                       int M, int K, int KC) {
    __shared__ float sA[64 * 32];
    const int tid = threadIdx.x, warp = tid >> 5, lane = tid & 31;
    const int rowBase = blockIdx.x * 64;
    const int nStages = (KC + 1) >> 1;

    float acc[8][4];
#pragma unroll
    for (int nt = 0; nt < 8; ++nt)
#pragma unroll
        for (int j = 0; j < 4; ++j) acc[nt][j] = 0.f;

    const int cr0 = warp * 16 + (lane >> 2);
    const int cr1 = cr0 + 8;
    const int sw0 = (cr0 & 3) << 3;
    const int sw1 = (cr1 & 3) << 3;

    float rbufA[16], rbufB[16];

#define LOADSTAGE(ST, RB)                                                      \
    do {                                                                       \
        int cBase = (ST) * 32;                                                 \
        int gc = cBase + lane;                                                 \
        bool cok = gc < K;                                                     \
        _Pragma("unroll")                                                      \
        for (int i = 0; i < 16; ++i) {                                         \
            int gr = rowBase + i * 4 + warp;                                   \
            RB[i] = (gr < M && cok) ? __ldg(A + (long)gr * K + gc) : 0.f;      \
        }                                                                      \
    } while (0)

#define COMMITSTAGE(RB)                                                        \
    do {                                                                       \
        _Pragma("unroll")                                                      \
        for (int i = 0; i < 16; ++i) {                                         \
            int rr = i * 4 + warp;                                             \
            sA[rr * 32 + (lane ^ ((rr & 3) << 3))] = RB[i];                    \
        }                                                                      \
    } while (0)

#define MMASTAGE(ST)                                                           \
    do {                                                                       \
        _Pragma("unroll")                                                      \
        for (int half = 0; half < 2; ++half) {                                 \
            int kc = (ST) * 2 + half;                                          \
            if (kc < KC) {                                                     \
                int c0 = half * 16 + (lane & 3) * 2;                           \
                float2 fA = *(const float2*)&sA[cr0 * 32 + ((c0    ) ^ sw0)];  \
                float2 fB = *(const float2*)&sA[cr1 * 32 + ((c0    ) ^ sw1)];  \
                float2 fC = *(const float2*)&sA[cr0 * 32 + ((c0 + 8) ^ sw0)];  \
                float2 fD = *(const float2*)&sA[cr1 * 32 + ((c0 + 8) ^ sw1)];  \
                unsigned ahi[4], alo[4];                                       \
                split2(fA.x, fA.y, ahi[0], alo[0]);                            \
                split2(fB.x, fB.y, ahi[1], alo[1]);                            \
                split2(fC.x, fC.y, ahi[2], alo[2]);                            \
                split2(fD.x, fD.y, ahi[3], alo[3]);                            \
                const uint4* bp = Bp + (size_t)kc * 256 + lane;                \
                _Pragma("unroll")                                              \
                for (int nt = 0; nt < 8; ++nt) {                               \
                    uint4 b = __ldg(&bp[nt * 32]);                             \
                    mma16816(acc[nt], ahi, b.x, b.y);                          \
                    mma16816(acc[nt], alo, b.x, b.y);                          \
                    mma16816(acc[nt], ahi, b.z, b.w);                          \
                }                                                              \
            }                                                                  \
        }                                                                      \
    } while (0)

    LOADSTAGE(0, rbufA);
    if (nStages > 1) LOADSTAGE(1, rbufB);
    for (int st = 0; st < nStages; st += 2) {
        // even stage (data in rbufA)
        COMMITSTAGE(rbufA);
        __syncthreads();
        if (st + 2 < nStages) LOADSTAGE(st + 2, rbufA);
        MMASTAGE(st);
        __syncthreads();
        if (st + 1 < nStages) {
            // odd stage (data in rbufB)
            COMMITSTAGE(rbufB);
            __syncthreads();
            if (st + 3 < nStages) LOADSTAGE(st + 3, rbufB);
            MMASTAGE(st + 1);
            __syncthreads();
        }
    }
#undef LOADSTAGE
#undef COMMITSTAGE
#undef MMASTAGE

    const int cbase = (lane & 3) * 2;
    const int gr[2] = { rowBase + cr0, rowBase + cr1 };
    float hv[2][8][2];          // row values in A-fragment layout
    float sum[2] = {0.f, 0.f}, sq[2] = {0.f, 0.f};

    if (EPI == 1) {
        // embedding: bias add, store x0, LN -> hv
#pragma unroll
        for (int f = 0; f < 2; ++f)
#pragma unroll
            for (int nt = 0; nt < 8; ++nt) {
                int cc = nt * 8 + cbase;
                float a0 = acc[nt][2 * f]     + bias_gw[cc];
                float a1 = acc[nt][2 * f + 1] + bias_gw[cc + 1];
                hv[f][nt][0] = a0; hv[f][nt][1] = a1;
                sum[f] += a0 + a1;
                sq[f]  += a0 * a0 + a1 * a1;
                if (gr[f] < M)
                    *(float2*)(O0 + (long)gr[f] * 64 + cc) = make_float2(a0, a1);
            }
    } else {
        // EPI 2: gated residual + alpha mix
        const float* gw = bias_gw;
        float rr[2][8][2], zz[2][8][2];
        float s[2] = {0.f, 0.f};
#pragma unroll
        for (int f = 0; f < 2; ++f) {
            bool ok = gr[f] < M;
#pragma unroll
            for (int nt = 0; nt < 8; ++nt) {
                int cc = nt * 8 + cbase;
                float2 rv = ok ? *(const float2*)(res + (long)gr[f] * 64 + cc)
                               : make_float2(0.f, 0.f);
                float2 zv = ok ? *(const float2*)(x0p + (long)gr[f] * 64 + cc)
                               : make_float2(0.f, 0.f);
                rr[f][nt][0] = rv.x; rr[f][nt][1] = rv.y;
                zz[f][nt][0] = zv.x; zz[f][nt][1] = zv.y;
                float o0 = acc[nt][2 * f], o1 = acc[nt][2 * f + 1];
                s[f] += o0 * gw[cc]        + o1 * gw[cc + 1]
                      + rv.x * gw[64 + cc] + rv.y * gw[65 + cc]
                      + (o0 - rv.x) * gw[128 + cc] + (o1 - rv.y) * gw[129 + cc];
            }
        }
#pragma unroll
        for (int o = 1; o <= 2; o <<= 1) {
            s[0] += __shfl_xor_sync(~0u, s[0], o);
            s[1] += __shfl_xor_sync(~0u, s[1], o);
        }
#pragma unroll
        for (int f = 0; f < 2; ++f) {
            float g = 1.f / (1.f + __expf(-(s[f] + gb[0])));
#pragma unroll
            for (int nt = 0; nt < 8; ++nt) {
                float o0 = acc[nt][2 * f], o1 = acc[nt][2 * f + 1];
                float n0 = ALPHA * (g * o0 + (1.f - g) * rr[f][nt][0])
                         + (1.f - ALPHA) * zz[f][nt][0];
                float n1 = ALPHA * (g * o1 + (1.f - g) * rr[f][nt][1])
                         + (1.f - ALPHA) * zz[f][nt][1];
                hv[f][nt][0] = n0; hv[f][nt][1] = n1;
                sum[f] += n0 + n1;
                sq[f]  += n0 * n0 + n1 * n1;
                if (gr[f] < M) {
                    int cc = nt * 8 + cbase;
                    *(float2*)(O0 + (long)gr[f] * 64 + cc) = make_float2(n0, n1);
                }
            }
        }
    }

    if (lns) {
        // LayerNorm in registers (quad reduction over the 4 lanes of a row)
#pragma unroll
        for (int o = 1; o <= 2; o <<= 1) {
            sum[0] += __shfl_xor_sync(~0u, sum[0], o);
            sum[1] += __shfl_xor_sync(~0u, sum[1], o);
            sq[0]  += __shfl_xor_sync(~0u, sq[0],  o);
            sq[1]  += __shfl_xor_sync(~0u, sq[1],  o);
        }
#pragma unroll
        for (int f = 0; f < 2; ++f) {
            float mu = sum[f] * (1.f / 64.f);
            float var = sq[f] * (1.f / 64.f) - mu * mu;
            float rstd = rsqrtf(var + 1e-5f);
#pragma unroll
            for (int nt = 0; nt < 8; ++nt) {
                int cc = nt * 8 + cbase;
                hv[f][nt][0] = (hv[f][nt][0] - mu) * rstd * lns[cc]     + lnb[cc];
                hv[f][nt][1] = (hv[f][nt][1] - mu) * rstd * lns[cc + 1] + lnb[cc + 1];
            }
        }
    }

    if (Bqkv) {
        // in-register QKV GEMMs: hv already sits in mma A-fragment layout
#pragma unroll
        for (int m = 0; m < 3; ++m) {
            float a2[8][4];
#pragma unroll
            for (int nt = 0; nt < 8; ++nt)
#pragma unroll
                for (int j = 0; j < 4; ++j) a2[nt][j] = 0.f;
#pragma unroll
            for (int kc = 0; kc < 4; ++kc) {
                unsigned ahi[4], alo[4];
                split2(hv[0][2*kc][0],   hv[0][2*kc][1],   ahi[0], alo[0]);
                split2(hv[1][2*kc][0],   hv[1][2*kc][1],   ahi[1], alo[1]);
                split2(hv[0][2*kc+1][0], hv[0][2*kc+1][1], ahi[2], alo[2]);
                split2(hv[1][2*kc+1][0], hv[1][2*kc+1][1], ahi[3], alo[3]);
                const uint4* bm = Bqkv + (size_t)m * 1024 + kc * 256 + lane;
#pragma unroll
                for (int nt = 0; nt < 8; ++nt) {
                    uint4 b = __ldg(&bm[nt * 32]);
                    mma16816(a2[nt], ahi, b.x, b.y);
                    mma16816(a2[nt], alo, b.x, b.y);
                    mma16816(a2[nt], ahi, b.z, b.w);
                }
            }
            if (m == 0) {
                // q in fp32
#pragma unroll
                for (int f = 0; f < 2; ++f) {
                    if (gr[f] >= M) continue;
#pragma unroll
                    for (int nt = 0; nt < 8; ++nt) {
                        int cc = nt * 8 + cbase;
                        *(float2*)(Oq + (long)gr[f] * 64 + cc) =
                            make_float2(a2[nt][2 * f], a2[nt][2 * f + 1]);
                    }
                }
            } else {
                // k/v packed half2
                unsigned* O2 = (m == 1) ? g_k2 : g_v2;
#pragma unroll
                for (int f = 0; f < 2; ++f) {
                    if (gr[f] >= M) continue;
#pragma unroll
                    for (int nt = 0; nt < 8; ++nt) {
                        __half2 hh = __floats2half2_rn(a2[nt][2 * f],
                                                       a2[nt][2 * f + 1]);
                        O2[(long)gr[f] * 32 + nt * 4 + (lane & 3)] =
                            *reinterpret_cast<unsigned*>(&hh);
                    }
                }
            }
        }
    }
}

// ---------------- CSR construction ----------------
__global__ void zero_deg_kernel() {
    int i = blockIdx.x * blockDim.x + threadIdx.x;
    if (i < NN) g_deg[i] = 0;
}

__global__ void hist_kernel(const int* __restrict__ ei) {
    int e = blockIdx.x * blockDim.x + threadIdx.x;
    if (e < EE) atomicAdd(&g_deg[ei[EE + e]], 1);
}

__global__ void scan_kernel() {
    __shared__ int ssum[1024];
    const int t = threadIdx.x;
    const int CHUNK = (NN + 1023) / 1024;
    int beg = t * CHUNK;
    int end = beg + CHUNK; if (end > NN) end = NN;
    int s = 0;
    for (int i = beg; i < end; ++i) s += g_deg[i];
    ssum[t] = s;
    __syncthreads();
    for (int d = 1; d < 1024; d <<= 1) {
        int v = (t >= d) ? ssum[t - d] : 0;
        __syncthreads();
        ssum[t] += v;
        __syncthreads();
    }
    int run = (t == 0) ? 0 : ssum[t - 1];
    for (int i = beg; i < end; ++i) {
        g_off[i] = run;
        g_pos[i] = run;
        run += g_deg[i];
    }
    if (t == 1023) g_off[NN] = ssum[1023];
}

__global__ void fill_kernel(const int* __restrict__ ei) {
    int e = blockIdx.x * blockDim.x + threadIdx.x;
    if (e < EE) {
        int d = ei[EE + e];
        int p = atomicAdd(&g_pos[d], 1);
        g_csr[p] = ei[e];
    }
}

// ---------------- fused edge attention: warp per dst, half2 k/v ------------
__global__ __launch_bounds__(256)
void attn_kernel() {
    int warp = (blockIdx.x * blockDim.x + threadIdx.x) >> 5;
    int lane = threadIdx.x & 31;
    if (warp >= NN) return;
    float2 qv = ((const float2*)(g_q + (size_t)warp * 64))[lane];
    qv.x *= 0.25f; qv.y *= 0.25f;      // fold DH^-0.5
    float l = 0.f, lB = 0.f;
    float ax = 0.f, ay = 0.f, bx = 0.f, by = 0.f;
    int beg = g_off[warp], end = g_off[warp + 1];
    int e = beg;
    for (; e + 1 < end; e += 2) {
        int s0 = g_csr[e], s1 = g_csr[e + 1];
        unsigned kw0 = g_k2[(size_t)s0 * 32 + lane];
        unsigned vw0 = g_v2[(size_t)s0 * 32 + lane];
        unsigned kw1 = g_k2[(size_t)s1 * 32 + lane];
        unsigned vw1 = g_v2[(size_t)s1 * 32 + lane];
        float2 k0 = h2f2(kw0), v0 = h2f2(vw0);
        float2 k1 = h2f2(kw1), v1 = h2f2(vw1);
        float d0 = qv.x * k0.x + qv.y * k0.y;
        float d1 = qv.x * k1.x + qv.y * k1.y;
#pragma unroll
        for (int o = 4; o; o >>= 1) {
            d0 += __shfl_xor_sync(~0u, d0, o);
            d1 += __shfl_xor_sync(~0u, d1, o);
        }
        float p0 = __expf(d0), p1 = __expf(d1);
        l  += p0;  ax += p0 * v0.x;  ay += p0 * v0.y;
        lB += p1;  bx += p1 * v1.x;  by += p1 * v1.y;
    }
    if (e < end) {
        int s0 = g_csr[e];
        unsigned kw0 = g_k2[(size_t)s0 * 32 + lane];
        unsigned vw0 = g_v2[(size_t)s0 * 32 + lane];
        float2 k0 = h2f2(kw0), v0 = h2f2(vw0);
        float d0 = qv.x * k0.x + qv.y * k0.y;
#pragma unroll
        for (int o = 4; o; o >>= 1) d0 += __shfl_xor_sync(~0u, d0, o);
        float p0 = __expf(d0);
        l += p0; ax += p0 * v0.x; ay += p0 * v0.y;
    }
    l += lB; ax += bx; ay += by;
    float inv = 1.f / (l + 1e-9f);
    ((float2*)(g_agg + (size_t)warp * 64))[lane] = make_float2(ax * inv, ay * inv);
}

// ---------------- launch ----------------
extern "C" void kernel_launch(void* const* d_in, const int* in_sizes, int n_in,
                              void* d_out, int out_size) {
    const float* nodes = (const float*)d_in[0];
    const int*   ei    = (const int*)  d_in[1];
    const float* emb_W = (const float*)d_in[2];
    const float* emb_b = (const float*)d_in[3];
    const float* ln_s  = (const float*)d_in[4];
    const float* ln_b  = (const float*)d_in[5];
    const float* Wq    = (const float*)d_in[6];
    const float* Wk    = (const float*)d_in[7];
    const float* Wv    = (const float*)d_in[8];
    const float* Wo    = (const float*)d_in[9];
    const float* gW    = (const float*)d_in[10];
    const float* gb    = (const float*)d_in[11];
    float* out = (float*)d_out;

    float *px0, *px, *pagg, *pq;
    uint4 *pBemb, *pBw;
    cudaGetSymbolAddress((void**)&px0,  g_x0);
    cudaGetSymbolAddress((void**)&px,   g_x);
    cudaGetSymbolAddress((void**)&pagg, g_agg);
    cudaGetSymbolAddress((void**)&pq,   g_q);
    cudaGetSymbolAddress((void**)&pBemb, g_Bemb);
    cudaGetSymbolAddress((void**)&pBw,   g_Bw);

    const int gemmGrid = (NN + 63) / 64;     // 1563
    const int warpGrid = (NN + 7) / 8;

    // launches 1-3
    pack_b_kernel<<<(KC_EMB * 256 + 255) / 256, 256>>>(emb_W, pBemb, F_IN, KC_EMB);
    pack_w_kernel<<<(12 * 1024 + 255) / 256, 256>>>(Wq, Wk, Wv, Wo, pBw);
    zero_deg_kernel<<<(NN + 255) / 256, 256>>>();
    // launch 4 (ncu capture): embedding GEMM + bias + LN0 + QKV0, all fused
    gemm_fused_kernel<1><<<gemmGrid, 128>>>(
        nodes, pBemb, px0, emb_b, nullptr, nullptr, nullptr,
        ln_s, ln_b, pBw, pq, NN, F_IN, KC_EMB);
    // CSR build
    hist_kernel<<<(EE + 255) / 256, 256>>>(ei);
    scan_kernel<<<1, 1024>>>();
    fill_kernel<<<(EE + 255) / 256, 256>>>(ei);

    for (int l = 0; l < DEPTH; ++l) {
        attn_kernel<<<warpGrid, 256>>>();   // q,k,v -> agg
        const float* res = (l == 0) ? px0 : px;
        float* dst = (l == DEPTH - 1) ? out : px;
        const float* nls = (l == DEPTH - 1) ? nullptr : ln_s + (l + 1) * 64;
        const float* nlb = (l == DEPTH - 1) ? nullptr : ln_b + (l + 1) * 64;
        const uint4* bqkv = (l == DEPTH - 1) ? nullptr
                                             : pBw + (size_t)(l + 1) * 4 * 1024;
        // Wo GEMM + gate + alpha mix + next LN + next QKV, all fused
        gemm_fused_kernel<2><<<gemmGrid, 128>>>(
            pagg, pBw + (size_t)(l * 4 + 3) * 1024, dst,
            gW + l * 192, gb + l, res, px0, nls, nlb,
            bqkv, pq, NN, 64, 4);
    }
}

// round 14
// speedup vs baseline: 1.5720x; 1.5333x over previous
#include <cuda_runtime.h>
#include <cuda_bf16.h>
#include <cuda_fp16.h>
#include <math.h>

#define NN 100000
#define EE 1600000
#define F_IN 1433
#define DD 64
#define DEPTH 3
#define ALPHA 0.9f
#define KC_EMB 90   // ceil(1433/16)

// ---------------- scratch (static device globals) ----------------
__device__ float    g_x0[NN * DD];
__device__ float    g_x [NN * DD];
__device__ float    g_agg[NN * DD];
__device__ float    g_q [NN * DD];
__device__ unsigned g_k2[NN * 32];   // half2-packed k rows
__device__ unsigned g_v2[NN * 32];   // half2-packed v rows
__device__ int      g_deg[NN];
__device__ int      g_off[NN + 1];
__device__ int      g_pos[NN];
__device__ int      g_csr[EE];
__device__ uint4    g_Bemb[KC_EMB * 256];  // packed split-bf16 emb weight
__device__ uint4    g_Bw[12 * 1024];       // q,k,v,o x 3 layers (K=64 -> KC=4)

// ---------------- helpers ----------------
__device__ __forceinline__ void split2(float x, float y, unsigned& hi, unsigned& lo) {
    __nv_bfloat162 h = __floats2bfloat162_rn(x, y);
    float rx = x - __low2float(h);
    float ry = y - __high2float(h);
    __nv_bfloat162 l = __floats2bfloat162_rn(rx, ry);
    hi = *reinterpret_cast<unsigned*>(&h);
    lo = *reinterpret_cast<unsigned*>(&l);
}

__device__ __forceinline__ void mma16816(float* c, const unsigned* a,
                                         unsigned b0, unsigned b1) {
    asm volatile(
        "mma.sync.aligned.m16n8k16.row.col.f32.bf16.bf16.f32 "
        "{%0,%1,%2,%3},{%4,%5,%6,%7},{%8,%9},{%0,%1,%2,%3};\n"
        : "+f"(c[0]), "+f"(c[1]), "+f"(c[2]), "+f"(c[3])
        : "r"(a[0]), "r"(a[1]), "r"(a[2]), "r"(a[3]), "r"(b0), "r"(b1));
}

__device__ __forceinline__ float2 h2f2(unsigned w) {
    return __half22float2(*reinterpret_cast<__half2*>(&w));
}

// ---------------- B packing ----------------
__global__ void pack_b_kernel(const float* __restrict__ B, uint4* __restrict__ out,
                              int K, int KC) {
    int idx = blockIdx.x * blockDim.x + threadIdx.x;
    if (idx >= KC * 256) return;
    int lane = idx & 31, nt = (idx >> 5) & 7, kc = idx >> 8;
    int col = nt * 8 + (lane >> 2);
    int kr = kc * 16 + (lane & 3) * 2;
    float f0 = (kr     < K) ? B[(kr    ) * 64 + col] : 0.f;
    float f1 = (kr + 1 < K) ? B[(kr + 1) * 64 + col] : 0.f;
    float f2 = (kr + 8 < K) ? B[(kr + 8) * 64 + col] : 0.f;
    float f3 = (kr + 9 < K) ? B[(kr + 9) * 64 + col] : 0.f;
    unsigned h0, l0, h1, l1;
    split2(f0, f1, h0, l0);
    split2(f2, f3, h1, l1);
    out[idx] = make_uint4(h0, h1, l0, l1);
}

__global__ void pack_w_kernel(const float* __restrict__ Wq, const float* __restrict__ Wk,
                              const float* __restrict__ Wv, const float* __restrict__ Wo,
                              uint4* __restrict__ out) {
    int idx = blockIdx.x * blockDim.x + threadIdx.x;
    if (idx >= 12 * 1024) return;
    int m = idx >> 10;
    int l = m >> 2, w = m & 3;
    const float* B = (w == 0 ? Wq : w == 1 ? Wk : w == 2 ? Wv : Wo) + l * 4096;
    int rest = idx & 1023;
    int lane = rest & 31, nt = (rest >> 5) & 7, kc = rest >> 8;
    int col = nt * 8 + (lane >> 2);
    int kr = kc * 16 + (lane & 3) * 2;
    float f0 = B[(kr    ) * 64 + col];
    float f1 = B[(kr + 1) * 64 + col];
    float f2 = B[(kr + 8) * 64 + col];
    float f3 = B[(kr + 9) * 64 + col];
    unsigned h0, l0, h1, l1;
    split2(f0, f1, h0, l0);
    split2(f2, f3, h1, l1);
    out[idx] = make_uint4(h0, h1, l0, l1);
}

// ------- fused GEMM: main GEMM + (bias|gate) + LN + in-register QKV GEMMs --
// (R10 structure: single register-staged prefetch buffer, 114 regs)
template <int EPI>
__global__ __launch_bounds__(128)
void gemm_fused_kernel(const float* __restrict__ A, const uint4* __restrict__ Bp,
                       float* __restrict__ O0,
                       const float* __restrict__ bias_gw,
                       const float* __restrict__ gb,
                       const float* __restrict__ res,
                       const float* __restrict__ x0p,
                       const float* __restrict__ lns,
                       const float* __restrict__ lnb,
                       const uint4* __restrict__ Bqkv,
                       float* __restrict__ Oq,
                       int M, int K, int KC) {
    __shared__ float sA[64 * 32];
    const int tid = threadIdx.x, warp = tid >> 5, lane = tid & 31;
    const int rowBase = blockIdx.x * 64;
    const int nStages = (KC + 1) >> 1;

    float acc[8][4];
#pragma unroll
    for (int nt = 0; nt < 8; ++nt)
#pragma unroll
        for (int j = 0; j < 4; ++j) acc[nt][j] = 0.f;

    const int cr0 = warp * 16 + (lane >> 2);
    const int cr1 = cr0 + 8;
    const int sw0 = (cr0 & 3) << 3;
    const int sw1 = (cr1 & 3) << 3;

    float rbuf[16];

#define LOADSTAGE(ST)                                                          \
    do {                                                                       \
        int cBase = (ST) * 32;                                                 \
        int gc = cBase + lane;                                                 \
        bool cok = gc < K;                                                     \
        _Pragma("unroll")                                                      \
        for (int i = 0; i < 16; ++i) {                                         \
            int gr = rowBase + i * 4 + warp;                                   \
            rbuf[i] = (gr < M && cok) ? __ldg(A + (long)gr * K + gc) : 0.f;    \
        }                                                                      \
    } while (0)

    LOADSTAGE(0);
    for (int st = 0; st < nStages; ++st) {
#pragma unroll
        for (int i = 0; i < 16; ++i) {
            int rr = i * 4 + warp;
            sA[rr * 32 + (lane ^ ((rr & 3) << 3))] = rbuf[i];
        }
        __syncthreads();
        if (st + 1 < nStages) LOADSTAGE(st + 1);
#pragma unroll
        for (int half = 0; half < 2; ++half) {
            int kc = st * 2 + half;
            if (kc < KC) {
                int c0 = half * 16 + (lane & 3) * 2;
                float2 fA = *(const float2*)&sA[cr0 * 32 + ((c0    ) ^ sw0)];
                float2 fB = *(const float2*)&sA[cr1 * 32 + ((c0    ) ^ sw1)];
                float2 fC = *(const float2*)&sA[cr0 * 32 + ((c0 + 8) ^ sw0)];
                float2 fD = *(const float2*)&sA[cr1 * 32 + ((c0 + 8) ^ sw1)];
                unsigned ahi[4], alo[4];
                split2(fA.x, fA.y, ahi[0], alo[0]);
                split2(fB.x, fB.y, ahi[1], alo[1]);
                split2(fC.x, fC.y, ahi[2], alo[2]);
                split2(fD.x, fD.y, ahi[3], alo[3]);
                const uint4* bp = Bp + (size_t)kc * 256 + lane;
#pragma unroll
                for (int nt = 0; nt < 8; ++nt) {
                    uint4 b = __ldg(&bp[nt * 32]);
                    mma16816(acc[nt], ahi, b.x, b.y);
                    mma16816(acc[nt], alo, b.x, b.y);
                    mma16816(acc[nt], ahi, b.z, b.w);
                }
            }
        }
        __syncthreads();
    }
#undef LOADSTAGE

    const int cbase = (lane & 3) * 2;
    const int gr[2] = { rowBase + cr0, rowBase + cr1 };
    float hv[2][8][2];          // row values in A-fragment layout
    float sum[2] = {0.f, 0.f}, sq[2] = {0.f, 0.f};

    if (EPI == 1) {
        // embedding: bias add, store x0, LN -> hv
#pragma unroll
        for (int f = 0; f < 2; ++f)
#pragma unroll
            for (int nt = 0; nt < 8; ++nt) {
                int cc = nt * 8 + cbase;
                float a0 = acc[nt][2 * f]     + bias_gw[cc];
                float a1 = acc[nt][2 * f + 1] + bias_gw[cc + 1];
                hv[f][nt][0] = a0; hv[f][nt][1] = a1;
                sum[f] += a0 + a1;
                sq[f]  += a0 * a0 + a1 * a1;
                if (gr[f] < M)
                    *(float2*)(O0 + (long)gr[f] * 64 + cc) = make_float2(a0, a1);
            }
    } else {
        // EPI 2: gated residual + alpha mix
        const float* gw = bias_gw;
        float rr[2][8][2], zz[2][8][2];
        float s[2] = {0.f, 0.f};
#pragma unroll
        for (int f = 0; f < 2; ++f) {
            bool ok = gr[f] < M;
#pragma unroll
            for (int nt = 0; nt < 8; ++nt) {
                int cc = nt * 8 + cbase;
                float2 rv = ok ? *(const float2*)(res + (long)gr[f] * 64 + cc)
                               : make_float2(0.f, 0.f);
                float2 zv = ok ? *(const float2*)(x0p + (long)gr[f] * 64 + cc)
                               : make_float2(0.f, 0.f);
                rr[f][nt][0] = rv.x; rr[f][nt][1] = rv.y;
                zz[f][nt][0] = zv.x; zz[f][nt][1] = zv.y;
                float o0 = acc[nt][2 * f], o1 = acc[nt][2 * f + 1];
                s[f] += o0 * gw[cc]        + o1 * gw[cc + 1]
                      + rv.x * gw[64 + cc] + rv.y * gw[65 + cc]
                      + (o0 - rv.x) * gw[128 + cc] + (o1 - rv.y) * gw[129 + cc];
            }
        }
#pragma unroll
        for (int o = 1; o <= 2; o <<= 1) {
            s[0] += __shfl_xor_sync(~0u, s[0], o);
            s[1] += __shfl_xor_sync(~0u, s[1], o);
        }
#pragma unroll
        for (int f = 0; f < 2; ++f) {
            float g = 1.f / (1.f + __expf(-(s[f] + gb[0])));
#pragma unroll
            for (int nt = 0; nt < 8; ++nt) {
                float o0 = acc[nt][2 * f], o1 = acc[nt][2 * f + 1];
                float n0 = ALPHA * (g * o0 + (1.f - g) * rr[f][nt][0])
                         + (1.f - ALPHA) * zz[f][nt][0];
                float n1 = ALPHA * (g * o1 + (1.f - g) * rr[f][nt][1])
                         + (1.f - ALPHA) * zz[f][nt][1];
                hv[f][nt][0] = n0; hv[f][nt][1] = n1;
                sum[f] += n0 + n1;
                sq[f]  += n0 * n0 + n1 * n1;
                if (gr[f] < M) {
                    int cc = nt * 8 + cbase;
                    *(float2*)(O0 + (long)gr[f] * 64 + cc) = make_float2(n0, n1);
                }
            }
        }
    }

    if (lns) {
        // LayerNorm in registers (quad reduction over the 4 lanes of a row)
#pragma unroll
        for (int o = 1; o <= 2; o <<= 1) {
            sum[0] += __shfl_xor_sync(~0u, sum[0], o);
            sum[1] += __shfl_xor_sync(~0u, sum[1], o);
            sq[0]  += __shfl_xor_sync(~0u, sq[0],  o);
            sq[1]  += __shfl_xor_sync(~0u, sq[1],  o);
        }
#pragma unroll
        for (int f = 0; f < 2; ++f) {
            float mu = sum[f] * (1.f / 64.f);
            float var = sq[f] * (1.f / 64.f) - mu * mu;
            float rstd = rsqrtf(var + 1e-5f);
#pragma unroll
            for (int nt = 0; nt < 8; ++nt) {
                int cc = nt * 8 + cbase;
                hv[f][nt][0] = (hv[f][nt][0] - mu) * rstd * lns[cc]     + lnb[cc];
                hv[f][nt][1] = (hv[f][nt][1] - mu) * rstd * lns[cc + 1] + lnb[cc + 1];
            }
        }
    }

    if (Bqkv) {
        // in-register QKV GEMMs: hv already sits in mma A-fragment layout
#pragma unroll
        for (int m = 0; m < 3; ++m) {
            float a2[8][4];
#pragma unroll
            for (int nt = 0; nt < 8; ++nt)
#pragma unroll
                for (int j = 0; j < 4; ++j) a2[nt][j] = 0.f;
#pragma unroll
            for (int kc = 0; kc < 4; ++kc) {
                unsigned ahi[4], alo[4];
                split2(hv[0][2*kc][0],   hv[0][2*kc][1],   ahi[0], alo[0]);
                split2(hv[1][2*kc][0],   hv[1][2*kc][1],   ahi[1], alo[1]);
                split2(hv[0][2*kc+1][0], hv[0][2*kc+1][1], ahi[2], alo[2]);
                split2(hv[1][2*kc+1][0], hv[1][2*kc+1][1], ahi[3], alo[3]);
                const uint4* bm = Bqkv + (size_t)m * 1024 + kc * 256 + lane;
#pragma unroll
                for (int nt = 0; nt < 8; ++nt) {
                    uint4 b = __ldg(&bm[nt * 32]);
                    mma16816(a2[nt], ahi, b.x, b.y);
                    mma16816(a2[nt], alo, b.x, b.y);
                    mma16816(a2[nt], ahi, b.z, b.w);
                }
            }
            if (m == 0) {
                // q in fp32
#pragma unroll
                for (int f = 0; f < 2; ++f) {
                    if (gr[f] >= M) continue;
#pragma unroll
                    for (int nt = 0; nt < 8; ++nt) {
                        int cc = nt * 8 + cbase;
                        *(float2*)(Oq + (long)gr[f] * 64 + cc) =
                            make_float2(a2[nt][2 * f], a2[nt][2 * f + 1]);
                    }
                }
            } else {
                // k/v packed half2
                unsigned* O2 = (m == 1) ? g_k2 : g_v2;
#pragma unroll
                for (int f = 0; f < 2; ++f) {
                    if (gr[f] >= M) continue;
#pragma unroll
                    for (int nt = 0; nt < 8; ++nt) {
                        __half2 hh = __floats2half2_rn(a2[nt][2 * f],
                                                       a2[nt][2 * f + 1]);
                        O2[(long)gr[f] * 32 + nt * 4 + (lane & 3)] =
                            *reinterpret_cast<unsigned*>(&hh);
                    }
                }
            }
        }
    }
}

// ---------------- CSR construction ----------------
__global__ void zero_deg_kernel() {
    int i = blockIdx.x * blockDim.x + threadIdx.x;
    if (i < NN) g_deg[i] = 0;
}

__global__ void hist_kernel(const int* __restrict__ ei) {
    int e = blockIdx.x * blockDim.x + threadIdx.x;
    if (e < EE) atomicAdd(&g_deg[ei[EE + e]], 1);
}

__global__ void scan_kernel() {
    __shared__ int ssum[1024];
    const int t = threadIdx.x;
    const int CHUNK = (NN + 1023) / 1024;
    int beg = t * CHUNK;
    int end = beg + CHUNK; if (end > NN) end = NN;
    int s = 0;
    for (int i = beg; i < end; ++i) s += g_deg[i];
    ssum[t] = s;
    __syncthreads();
    for (int d = 1; d < 1024; d <<= 1) {
        int v = (t >= d) ? ssum[t - d] : 0;
        __syncthreads();
        ssum[t] += v;
        __syncthreads();
    }
    int run = (t == 0) ? 0 : ssum[t - 1];
    for (int i = beg; i < end; ++i) {
        g_off[i] = run;
        g_pos[i] = run;
        run += g_deg[i];
    }
    if (t == 1023) g_off[NN] = ssum[1023];
}

__global__ void fill_kernel(const int* __restrict__ ei) {
    int e = blockIdx.x * blockDim.x + threadIdx.x;
    if (e < EE) {
        int d = ei[EE + e];
        int p = atomicAdd(&g_pos[d], 1);
        g_csr[p] = ei[e];
    }
}

// ---- fused edge attention: warp per dst, half2 k/v, csr index prefetch ----
__global__ __launch_bounds__(256)
void attn_kernel() {
    int warp = (blockIdx.x * blockDim.x + threadIdx.x) >> 5;
    int lane = threadIdx.x & 31;
    if (warp >= NN) return;
    float2 qv = ((const float2*)(g_q + (size_t)warp * 64))[lane];
    qv.x *= 0.25f; qv.y *= 0.25f;      // fold DH^-0.5
    float l = 0.f, lB = 0.f;
    float ax = 0.f, ay = 0.f, bx = 0.f, by = 0.f;
    int beg = g_off[warp], end = g_off[warp + 1];
    int e = beg;
    // prefetch first pair of source indices
    int nxt0 = (e     < end) ? g_csr[e]     : 0;
    int nxt1 = (e + 1 < end) ? g_csr[e + 1] : 0;
    for (; e + 1 < end; e += 2) {
        int s0 = nxt0, s1 = nxt1;
        // prefetch NEXT pair while this pair's k/v gathers are in flight
        if (e + 2 < end) nxt0 = g_csr[e + 2];
        if (e + 3 < end) nxt1 = g_csr[e + 3];
        unsigned kw0 = g_k2[(size_t)s0 * 32 + lane];
        unsigned vw0 = g_v2[(size_t)s0 * 32 + lane];
        unsigned kw1 = g_k2[(size_t)s1 * 32 + lane];
        unsigned vw1 = g_v2[(size_t)s1 * 32 + lane];
        float2 k0 = h2f2(kw0), v0 = h2f2(vw0);
        float2 k1 = h2f2(kw1), v1 = h2f2(vw1);
        float d0 = qv.x * k0.x + qv.y * k0.y;
        float d1 = qv.x * k1.x + qv.y * k1.y;
#pragma unroll
        for (int o = 4; o; o >>= 1) {
            d0 += __shfl_xor_sync(~0u, d0, o);
            d1 += __shfl_xor_sync(~0u, d1, o);
        }
        float p0 = __expf(d0), p1 = __expf(d1);
        l  += p0;  ax += p0 * v0.x;  ay += p0 * v0.y;
        lB += p1;  bx += p1 * v1.x;  by += p1 * v1.y;
    }
    if (e < end) {
        int s0 = nxt0;
        unsigned kw0 = g_k2[(size_t)s0 * 32 + lane];
        unsigned vw0 = g_v2[(size_t)s0 * 32 + lane];
        float2 k0 = h2f2(kw0), v0 = h2f2(vw0);
        float d0 = qv.x * k0.x + qv.y * k0.y;
#pragma unroll
        for (int o = 4; o; o >>= 1) d0 += __shfl_xor_sync(~0u, d0, o);
        float p0 = __expf(d0);
        l += p0; ax += p0 * v0.x; ay += p0 * v0.y;
    }
    l += lB; ax += bx; ay += by;
    float inv = 1.f / (l + 1e-9f);
    ((float2*)(g_agg + (size_t)warp * 64))[lane] = make_float2(ax * inv, ay * inv);
}

// ---------------- launch ----------------
extern "C" void kernel_launch(void* const* d_in, const int* in_sizes, int n_in,
                              void* d_out, int out_size) {
    const float* nodes = (const float*)d_in[0];
    const int*   ei    = (const int*)  d_in[1];
    const float* emb_W = (const float*)d_in[2];
    const float* emb_b = (const float*)d_in[3];
    const float* ln_s  = (const float*)d_in[4];
    const float* ln_b  = (const float*)d_in[5];
    const float* Wq    = (const float*)d_in[6];
    const float* Wk    = (const float*)d_in[7];
    const float* Wv    = (const float*)d_in[8];
    const float* Wo    = (const float*)d_in[9];
    const float* gW    = (const float*)d_in[10];
    const float* gb    = (const float*)d_in[11];
    float* out = (float*)d_out;

    float *px0, *px, *pagg, *pq;
    uint4 *pBemb, *pBw;
    cudaGetSymbolAddress((void**)&px0,  g_x0);
    cudaGetSymbolAddress((void**)&px,   g_x);
    cudaGetSymbolAddress((void**)&pagg, g_agg);
    cudaGetSymbolAddress((void**)&pq,   g_q);
    cudaGetSymbolAddress((void**)&pBemb, g_Bemb);
    cudaGetSymbolAddress((void**)&pBw,   g_Bw);

    const int gemmGrid = (NN + 63) / 64;     // 1563
    const int warpGrid = (NN + 7) / 8;

    // launches 1-3
    pack_b_kernel<<<(KC_EMB * 256 + 255) / 256, 256>>>(emb_W, pBemb, F_IN, KC_EMB);
    pack_w_kernel<<<(12 * 1024 + 255) / 256, 256>>>(Wq, Wk, Wv, Wo, pBw);
    zero_deg_kernel<<<(NN + 255) / 256, 256>>>();
    // launch 4 (ncu capture): embedding GEMM + bias + LN0 + QKV0, all fused
    gemm_fused_kernel<1><<<gemmGrid, 128>>>(
        nodes, pBemb, px0, emb_b, nullptr, nullptr, nullptr,
        ln_s, ln_b, pBw, pq, NN, F_IN, KC_EMB);
    // CSR build
    hist_kernel<<<(EE + 255) / 256, 256>>>(ei);
    scan_kernel<<<1, 1024>>>();
    fill_kernel<<<(EE + 255) / 256, 256>>>(ei);

    for (int l = 0; l < DEPTH; ++l) {
        attn_kernel<<<warpGrid, 256>>>();   // q,k,v -> agg
        const float* res = (l == 0) ? px0 : px;
        float* dst = (l == DEPTH - 1) ? out : px;
        const float* nls = (l == DEPTH - 1) ? nullptr : ln_s + (l + 1) * 64;
        const float* nlb = (l == DEPTH - 1) ? nullptr : ln_b + (l + 1) * 64;
        const uint4* bqkv = (l == DEPTH - 1) ? nullptr
                                             : pBw + (size_t)(l + 1) * 4 * 1024;
        // Wo GEMM + gate + alpha mix + next LN + next QKV, all fused
        gemm_fused_kernel<2><<<gemmGrid, 128>>>(
            pagg, pBw + (size_t)(l * 4 + 3) * 1024, dst,
            gW + l * 192, gb + l, res, px0, nls, nlb,
            bqkv, pq, NN, 64, 4);
    }
}

// round 15
// speedup vs baseline: 1.6432x; 1.0453x over previous
#include <cuda_runtime.h>
#include <cuda_bf16.h>
#include <cuda_fp16.h>
#include <math.h>

#define NN 100000
#define EE 1600000
#define F_IN 1433
#define DD 64
#define DEPTH 3
#define ALPHA 0.9f
#define KC_EMB 90   // ceil(1433/16)

// ---------------- scratch (static device globals) ----------------
__device__ float    g_x0[NN * DD];
__device__ float    g_x [NN * DD];
__device__ float    g_agg[NN * DD];
__device__ float    g_q [NN * DD];
__device__ unsigned g_k2[NN * 32];   // half2-packed k rows
__device__ unsigned g_v2[NN * 32];   // half2-packed v rows
__device__ int      g_deg[NN];
__device__ int      g_off[NN + 1];
__device__ int      g_pos[NN];
__device__ int      g_csr[EE];
__device__ uint4    g_Bemb[KC_EMB * 256];  // packed split-bf16 emb weight
__device__ uint4    g_Bw[12 * 1024];       // q,k,v,o x 3 layers (K=64 -> KC=4)

// ---------------- helpers ----------------
__device__ __forceinline__ void split2(float x, float y, unsigned& hi, unsigned& lo) {
    __nv_bfloat162 h = __floats2bfloat162_rn(x, y);
    float rx = x - __low2float(h);
    float ry = y - __high2float(h);
    __nv_bfloat162 l = __floats2bfloat162_rn(rx, ry);
    hi = *reinterpret_cast<unsigned*>(&h);
    lo = *reinterpret_cast<unsigned*>(&l);
}

__device__ __forceinline__ void mma16816(float* c, const unsigned* a,
                                         unsigned b0, unsigned b1) {
    asm volatile(
        "mma.sync.aligned.m16n8k16.row.col.f32.bf16.bf16.f32 "
        "{%0,%1,%2,%3},{%4,%5,%6,%7},{%8,%9},{%0,%1,%2,%3};\n"
        : "+f"(c[0]), "+f"(c[1]), "+f"(c[2]), "+f"(c[3])
        : "r"(a[0]), "r"(a[1]), "r"(a[2]), "r"(a[3]), "r"(b0), "r"(b1));
}

__device__ __forceinline__ float2 h2f2(unsigned w) {
    return __half22float2(*reinterpret_cast<__half2*>(&w));
}

// ---------------- B packing ----------------
__global__ void pack_b_kernel(const float* __restrict__ B, uint4* __restrict__ out,
                              int K, int KC) {
    int idx = blockIdx.x * blockDim.x + threadIdx.x;
    if (idx >= KC * 256) return;
    int lane = idx & 31, nt = (idx >> 5) & 7, kc = idx >> 8;
    int col = nt * 8 + (lane >> 2);
    int kr = kc * 16 + (lane & 3) * 2;
    float f0 = (kr     < K) ? B[(kr    ) * 64 + col] : 0.f;
    float f1 = (kr + 1 < K) ? B[(kr + 1) * 64 + col] : 0.f;
    float f2 = (kr + 8 < K) ? B[(kr + 8) * 64 + col] : 0.f;
    float f3 = (kr + 9 < K) ? B[(kr + 9) * 64 + col] : 0.f;
    unsigned h0, l0, h1, l1;
    split2(f0, f1, h0, l0);
    split2(f2, f3, h1, l1);
    out[idx] = make_uint4(h0, h1, l0, l1);
}

__global__ void pack_w_kernel(const float* __restrict__ Wq, const float* __restrict__ Wk,
                              const float* __restrict__ Wv, const float* __restrict__ Wo,
                              uint4* __restrict__ out) {
    int idx = blockIdx.x * blockDim.x + threadIdx.x;
    if (idx >= 12 * 1024) return;
    int m = idx >> 10;
    int l = m >> 2, w = m & 3;
    const float* B = (w == 0 ? Wq : w == 1 ? Wk : w == 2 ? Wv : Wo) + l * 4096;
    int rest = idx & 1023;
    int lane = rest & 31, nt = (rest >> 5) & 7, kc = rest >> 8;
    int col = nt * 8 + (lane >> 2);
    int kr = kc * 16 + (lane & 3) * 2;
    float f0 = B[(kr    ) * 64 + col];
    float f1 = B[(kr + 1) * 64 + col];
    float f2 = B[(kr + 8) * 64 + col];
    float f3 = B[(kr + 9) * 64 + col];
    unsigned h0, l0, h1, l1;
    split2(f0, f1, h0, l0);
    split2(f2, f3, h1, l1);
    out[idx] = make_uint4(h0, h1, l0, l1);
}

// ------- fused GEMM: main GEMM + (bias|gate) + LN + in-register QKV GEMMs --
// A staged via 4-byte cp.async (alignment-safe for stride-K rows) into a
// double-buffered smem slab; hardware async pipeline, no register buffer.
template <int EPI>
__global__ __launch_bounds__(128)
void gemm_fused_kernel(const float* __restrict__ A, const uint4* __restrict__ Bp,
                       float* __restrict__ O0,
                       const float* __restrict__ bias_gw,
                       const float* __restrict__ gb,
                       const float* __restrict__ res,
                       const float* __restrict__ x0p,
                       const float* __restrict__ lns,
                       const float* __restrict__ lnb,
                       const uint4* __restrict__ Bqkv,
                       float* __restrict__ Oq,
                       int M, int K, int KC) {
    __shared__ float sA[2][64 * 32];
    const int tid = threadIdx.x, warp = tid >> 5, lane = tid & 31;
    const int rowBase = blockIdx.x * 64;
    const int nStages = (KC + 1) >> 1;

    float acc[8][4];
#pragma unroll
    for (int nt = 0; nt < 8; ++nt)
#pragma unroll
        for (int j = 0; j < 4; ++j) acc[nt][j] = 0.f;

    const int cr0 = warp * 16 + (lane >> 2);
    const int cr1 = cr0 + 8;
    const int sw0 = (cr0 & 3) << 3;
    const int sw1 = (cr1 & 3) << 3;

    // producer: thread covers rows {warp, warp+4, ..., warp+60}, col = lane
    // 4-byte cp.async with src-size zfill for row/col tails.
#define PREFETCH(ST, BUF)                                                      \
    do {                                                                       \
        int gc = (ST) * 32 + lane;                                             \
        bool cok = gc < K;                                                     \
        _Pragma("unroll")                                                      \
        for (int i = 0; i < 16; ++i) {                                         \
            int rr = i * 4 + warp;                                             \
            int gr = rowBase + rr;                                             \
            bool ok = (gr < M) && cok;                                         \
            int sz = ok ? 4 : 0;                                               \
            const float* src = ok ? (A + (long)gr * K + gc) : A;               \
            unsigned dst = (unsigned)__cvta_generic_to_shared(                 \
                &sA[BUF][rr * 32 + (lane ^ ((rr & 3) << 3))]);                 \
            asm volatile("cp.async.ca.shared.global [%0], [%1], 4, %2;\n"      \
                         :: "r"(dst), "l"(src), "r"(sz));                      \
        }                                                                      \
        asm volatile("cp.async.commit_group;\n");                              \
    } while (0)

    PREFETCH(0, 0);
    for (int st = 0; st < nStages; ++st) {
        const int buf = st & 1;
        if (st + 1 < nStages) PREFETCH(st + 1, buf ^ 1);
        else asm volatile("cp.async.commit_group;\n");
        asm volatile("cp.async.wait_group 1;\n");
        __syncthreads();
#pragma unroll
        for (int half = 0; half < 2; ++half) {
            int kc = st * 2 + half;
            if (kc < KC) {
                int c0 = half * 16 + (lane & 3) * 2;
                const float* sb = sA[buf];
                float2 fA = *(const float2*)&sb[cr0 * 32 + ((c0    ) ^ sw0)];
                float2 fB = *(const float2*)&sb[cr1 * 32 + ((c0    ) ^ sw1)];
                float2 fC = *(const float2*)&sb[cr0 * 32 + ((c0 + 8) ^ sw0)];
                float2 fD = *(const float2*)&sb[cr1 * 32 + ((c0 + 8) ^ sw1)];
                unsigned ahi[4], alo[4];
                split2(fA.x, fA.y, ahi[0], alo[0]);
                split2(fB.x, fB.y, ahi[1], alo[1]);
                split2(fC.x, fC.y, ahi[2], alo[2]);
                split2(fD.x, fD.y, ahi[3], alo[3]);
                const uint4* bp = Bp + (size_t)kc * 256 + lane;
#pragma unroll
                for (int nt = 0; nt < 8; ++nt) {
                    uint4 b = __ldg(&bp[nt * 32]);
                    mma16816(acc[nt], ahi, b.x, b.y);
                    mma16816(acc[nt], alo, b.x, b.y);
                    mma16816(acc[nt], ahi, b.z, b.w);
                }
            }
        }
        __syncthreads();
    }
#undef PREFETCH

    const int cbase = (lane & 3) * 2;
    const int gr[2] = { rowBase + cr0, rowBase + cr1 };
    float hv[2][8][2];          // row values in A-fragment layout
    float sum[2] = {0.f, 0.f}, sq[2] = {0.f, 0.f};

    if (EPI == 1) {
        // embedding: bias add, store x0, LN -> hv
#pragma unroll
        for (int f = 0; f < 2; ++f)
#pragma unroll
            for (int nt = 0; nt < 8; ++nt) {
                int cc = nt * 8 + cbase;
                float a0 = acc[nt][2 * f]     + bias_gw[cc];
                float a1 = acc[nt][2 * f + 1] + bias_gw[cc + 1];
                hv[f][nt][0] = a0; hv[f][nt][1] = a1;
                sum[f] += a0 + a1;
                sq[f]  += a0 * a0 + a1 * a1;
                if (gr[f] < M)
                    *(float2*)(O0 + (long)gr[f] * 64 + cc) = make_float2(a0, a1);
            }
    } else {
        // EPI 2: gated residual + alpha mix
        const float* gw = bias_gw;
        float rr[2][8][2], zz[2][8][2];
        float s[2] = {0.f, 0.f};
#pragma unroll
        for (int f = 0; f < 2; ++f) {
            bool ok = gr[f] < M;
#pragma unroll
            for (int nt = 0; nt < 8; ++nt) {
                int cc = nt * 8 + cbase;
                float2 rv = ok ? *(const float2*)(res + (long)gr[f] * 64 + cc)
                               : make_float2(0.f, 0.f);
                float2 zv = ok ? *(const float2*)(x0p + (long)gr[f] * 64 + cc)
                               : make_float2(0.f, 0.f);
                rr[f][nt][0] = rv.x; rr[f][nt][1] = rv.y;
                zz[f][nt][0] = zv.x; zz[f][nt][1] = zv.y;
                float o0 = acc[nt][2 * f], o1 = acc[nt][2 * f + 1];
                s[f] += o0 * gw[cc]        + o1 * gw[cc + 1]
                      + rv.x * gw[64 + cc] + rv.y * gw[65 + cc]
                      + (o0 - rv.x) * gw[128 + cc] + (o1 - rv.y) * gw[129 + cc];
            }
        }
#pragma unroll
        for (int o = 1; o <= 2; o <<= 1) {
            s[0] += __shfl_xor_sync(~0u, s[0], o);
            s[1] += __shfl_xor_sync(~0u, s[1], o);
        }
#pragma unroll
        for (int f = 0; f < 2; ++f) {
            float g = 1.f / (1.f + __expf(-(s[f] + gb[0])));
#pragma unroll
            for (int nt = 0; nt < 8; ++nt) {
                float o0 = acc[nt][2 * f], o1 = acc[nt][2 * f + 1];
                float n0 = ALPHA * (g * o0 + (1.f - g) * rr[f][nt][0])
                         + (1.f - ALPHA) * zz[f][nt][0];
                float n1 = ALPHA * (g * o1 + (1.f - g) * rr[f][nt][1])
                         + (1.f - ALPHA) * zz[f][nt][1];
                hv[f][nt][0] = n0; hv[f][nt][1] = n1;
                sum[f] += n0 + n1;
                sq[f]  += n0 * n0 + n1 * n1;
                if (gr[f] < M) {
                    int cc = nt * 8 + cbase;
                    *(float2*)(O0 + (long)gr[f] * 64 + cc) = make_float2(n0, n1);
                }
            }
        }
    }

    if (lns) {
        // LayerNorm in registers (quad reduction over the 4 lanes of a row)
#pragma unroll
        for (int o = 1; o <= 2; o <<= 1) {
            sum[0] += __shfl_xor_sync(~0u, sum[0], o);
            sum[1] += __shfl_xor_sync(~0u, sum[1], o);
            sq[0]  += __shfl_xor_sync(~0u, sq[0],  o);
            sq[1]  += __shfl_xor_sync(~0u, sq[1],  o);
        }
#pragma unroll
        for (int f = 0; f < 2; ++f) {
            float mu = sum[f] * (1.f / 64.f);
            float var = sq[f] * (1.f / 64.f) - mu * mu;
            float rstd = rsqrtf(var + 1e-5f);
#pragma unroll
            for (int nt = 0; nt < 8; ++nt) {
                int cc = nt * 8 + cbase;
                hv[f][nt][0] = (hv[f][nt][0] - mu) * rstd * lns[cc]     + lnb[cc];
                hv[f][nt][1] = (hv[f][nt][1] - mu) * rstd * lns[cc + 1] + lnb[cc + 1];
            }
        }
    }

    if (Bqkv) {
        // in-register QKV GEMMs: hv already sits in mma A-fragment layout
#pragma unroll
        for (int m = 0; m < 3; ++m) {
            float a2[8][4];
#pragma unroll
            for (int nt = 0; nt < 8; ++nt)
#pragma unroll
                for (int j = 0; j < 4; ++j) a2[nt][j] = 0.f;
#pragma unroll
            for (int kc = 0; kc < 4; ++kc) {
                unsigned ahi[4], alo[4];
                split2(hv[0][2*kc][0],   hv[0][2*kc][1],   ahi[0], alo[0]);
                split2(hv[1][2*kc][0],   hv[1][2*kc][1],   ahi[1], alo[1]);
                split2(hv[0][2*kc+1][0], hv[0][2*kc+1][1], ahi[2], alo[2]);
                split2(hv[1][2*kc+1][0], hv[1][2*kc+1][1], ahi[3], alo[3]);
                const uint4* bm = Bqkv + (size_t)m * 1024 + kc * 256 + lane;
#pragma unroll
                for (int nt = 0; nt < 8; ++nt) {
                    uint4 b = __ldg(&bm[nt * 32]);
                    mma16816(a2[nt], ahi, b.x, b.y);
                    mma16816(a2[nt], alo, b.x, b.y);
                    mma16816(a2[nt], ahi, b.z, b.w);
                }
            }
            if (m == 0) {
                // q in fp32
#pragma unroll
                for (int f = 0; f < 2; ++f) {
                    if (gr[f] >= M) continue;
#pragma unroll
                    for (int nt = 0; nt < 8; ++nt) {
                        int cc = nt * 8 + cbase;
                        *(float2*)(Oq + (long)gr[f] * 64 + cc) =
                            make_float2(a2[nt][2 * f], a2[nt][2 * f + 1]);
                    }
                }
            } else {
                // k/v packed half2
                unsigned* O2 = (m == 1) ? g_k2 : g_v2;
#pragma unroll
                for (int f = 0; f < 2; ++f) {
                    if (gr[f] >= M) continue;
#pragma unroll
                    for (int nt = 0; nt < 8; ++nt) {
                        __half2 hh = __floats2half2_rn(a2[nt][2 * f],
                                                       a2[nt][2 * f + 1]);
                        O2[(long)gr[f] * 32 + nt * 4 + (lane & 3)] =
                            *reinterpret_cast<unsigned*>(&hh);
                    }
                }
            }
        }
    }
}

// ---------------- CSR construction ----------------
__global__ void zero_deg_kernel() {
    int i = blockIdx.x * blockDim.x + threadIdx.x;
    if (i < NN) g_deg[i] = 0;
}

__global__ void hist_kernel(const int* __restrict__ ei) {
    int e = blockIdx.x * blockDim.x + threadIdx.x;
    if (e < EE) atomicAdd(&g_deg[ei[EE + e]], 1);
}

__global__ void scan_kernel() {
    __shared__ int ssum[1024];
    const int t = threadIdx.x;
    const int CHUNK = (NN + 1023) / 1024;
    int beg = t * CHUNK;
    int end = beg + CHUNK; if (end > NN) end = NN;
    int s = 0;
    for (int i = beg; i < end; ++i) s += g_deg[i];
    ssum[t] = s;
    __syncthreads();
    for (int d = 1; d < 1024; d <<= 1) {
        int v = (t >= d) ? ssum[t - d] : 0;
        __syncthreads();
        ssum[t] += v;
        __syncthreads();
    }
    int run = (t == 0) ? 0 : ssum[t - 1];
    for (int i = beg; i < end; ++i) {
        g_off[i] = run;
        g_pos[i] = run;
        run += g_deg[i];
    }
    if (t == 1023) g_off[NN] = ssum[1023];
}

__global__ void fill_kernel(const int* __restrict__ ei) {
    int e = blockIdx.x * blockDim.x + threadIdx.x;
    if (e < EE) {
        int d = ei[EE + e];
        int p = atomicAdd(&g_pos[d], 1);
        g_csr[p] = ei[e];
    }
}

// ---------------- fused edge attention: warp per dst, half2 k/v (R10) ------
__global__ __launch_bounds__(256)
void attn_kernel() {
    int warp = (blockIdx.x * blockDim.x + threadIdx.x) >> 5;
    int lane = threadIdx.x & 31;
    if (warp >= NN) return;
    float2 qv = ((const float2*)(g_q + (size_t)warp * 64))[lane];
    qv.x *= 0.25f; qv.y *= 0.25f;      // fold DH^-0.5
    float l = 0.f, lB = 0.f;
    float ax = 0.f, ay = 0.f, bx = 0.f, by = 0.f;
    int beg = g_off[warp], end = g_off[warp + 1];
    int e = beg;
    for (; e + 1 < end; e += 2) {
        int s0 = g_csr[e], s1 = g_csr[e + 1];
        unsigned kw0 = g_k2[(size_t)s0 * 32 + lane];
        unsigned vw0 = g_v2[(size_t)s0 * 32 + lane];
        unsigned kw1 = g_k2[(size_t)s1 * 32 + lane];
        unsigned vw1 = g_v2[(size_t)s1 * 32 + lane];
        float2 k0 = h2f2(kw0), v0 = h2f2(vw0);
        float2 k1 = h2f2(kw1), v1 = h2f2(vw1);
        float d0 = qv.x * k0.x + qv.y * k0.y;
        float d1 = qv.x * k1.x + qv.y * k1.y;
#pragma unroll
        for (int o = 4; o; o >>= 1) {
            d0 += __shfl_xor_sync(~0u, d0, o);
            d1 += __shfl_xor_sync(~0u, d1, o);
        }
        float p0 = __expf(d0), p1 = __expf(d1);
        l  += p0;  ax += p0 * v0.x;  ay += p0 * v0.y;
        lB += p1;  bx += p1 * v1.x;  by += p1 * v1.y;
    }
    if (e < end) {
        int s0 = g_csr[e];
        unsigned kw0 = g_k2[(size_t)s0 * 32 + lane];
        unsigned vw0 = g_v2[(size_t)s0 * 32 + lane];
        float2 k0 = h2f2(kw0), v0 = h2f2(vw0);
        float d0 = qv.x * k0.x + qv.y * k0.y;
#pragma unroll
        for (int o = 4; o; o >>= 1) d0 += __shfl_xor_sync(~0u, d0, o);
        float p0 = __expf(d0);
        l += p0; ax += p0 * v0.x; ay += p0 * v0.y;
    }
    l += lB; ax += bx; ay += by;
    float inv = 1.f / (l + 1e-9f);
    ((float2*)(g_agg + (size_t)warp * 64))[lane] = make_float2(ax * inv, ay * inv);
}

// ---------------- launch ----------------
extern "C" void kernel_launch(void* const* d_in, const int* in_sizes, int n_in,
                              void* d_out, int out_size) {
    const float* nodes = (const float*)d_in[0];
    const int*   ei    = (const int*)  d_in[1];
    const float* emb_W = (const float*)d_in[2];
    const float* emb_b = (const float*)d_in[3];
    const float* ln_s  = (const float*)d_in[4];
    const float* ln_b  = (const float*)d_in[5];
    const float* Wq    = (const float*)d_in[6];
    const float* Wk    = (const float*)d_in[7];
    const float* Wv    = (const float*)d_in[8];
    const float* Wo    = (const float*)d_in[9];
    const float* gW    = (const float*)d_in[10];
    const float* gb    = (const float*)d_in[11];
    float* out = (float*)d_out;

    float *px0, *px, *pagg, *pq;
    uint4 *pBemb, *pBw;
    cudaGetSymbolAddress((void**)&px0,  g_x0);
    cudaGetSymbolAddress((void**)&px,   g_x);
    cudaGetSymbolAddress((void**)&pagg, g_agg);
    cudaGetSymbolAddress((void**)&pq,   g_q);
    cudaGetSymbolAddress((void**)&pBemb, g_Bemb);
    cudaGetSymbolAddress((void**)&pBw,   g_Bw);

    const int gemmGrid = (NN + 63) / 64;     // 1563
    const int warpGrid = (NN + 7) / 8;

    // launches 1-3
    pack_b_kernel<<<(KC_EMB * 256 + 255) / 256, 256>>>(emb_W, pBemb, F_IN, KC_EMB);
    pack_w_kernel<<<(12 * 1024 + 255) / 256, 256>>>(Wq, Wk, Wv, Wo, pBw);
    zero_deg_kernel<<<(NN + 255) / 256, 256>>>();
    // launch 4 (ncu capture): embedding GEMM + bias + LN0 + QKV0, all fused
    gemm_fused_kernel<1><<<gemmGrid, 128>>>(
        nodes, pBemb, px0, emb_b, nullptr, nullptr, nullptr,
        ln_s, ln_b, pBw, pq, NN, F_IN, KC_EMB);
    // CSR build
    hist_kernel<<<(EE + 255) / 256, 256>>>(ei);
    scan_kernel<<<1, 1024>>>();
    fill_kernel<<<(EE + 255) / 256, 256>>>(ei);

    for (int l = 0; l < DEPTH; ++l) {
        attn_kernel<<<warpGrid, 256>>>();   // q,k,v -> agg
        const float* res = (l == 0) ? px0 : px;
        float* dst = (l == DEPTH - 1) ? out : px;
        const float* nls = (l == DEPTH - 1) ? nullptr : ln_s + (l + 1) * 64;
        const float* nlb = (l == DEPTH - 1) ? nullptr : ln_b + (l + 1) * 64;
        const uint4* bqkv = (l == DEPTH - 1) ? nullptr
                                             : pBw + (size_t)(l + 1) * 4 * 1024;
        // Wo GEMM + gate + alpha mix + next LN + next QKV, all fused
        gemm_fused_kernel<2><<<gemmGrid, 128>>>(
            pagg, pBw + (size_t)(l * 4 + 3) * 1024, dst,
            gW + l * 192, gb + l, res, px0, nls, nlb,
            bqkv, pq, NN, 64, 4);
    }
}

// round 16
// speedup vs baseline: 2.0906x; 1.2723x over previous
#include <cuda_runtime.h>
#include <cuda_bf16.h>
#include <cuda_fp16.h>
#include <math.h>

#define NN 100000
#define EE 1600000
#define F_IN 1433
#define DD 64
#define DEPTH 3
#define ALPHA 0.9f
#define KC_EMB 90   // ceil(1433/16)

// ---------------- scratch (static device globals) ----------------
__device__ float    g_x0[NN * DD];
__device__ float    g_x [NN * DD];
__device__ float    g_agg[NN * DD];
__device__ float    g_q [NN * DD];
__device__ unsigned g_k2[NN * 32];   // half2-packed k rows
__device__ unsigned g_v2[NN * 32];   // half2-packed v rows
__device__ int      g_deg[NN];
__device__ int      g_off[NN + 1];
__device__ int      g_pos[NN];
__device__ int      g_csr[EE];
__device__ uint4    g_Bemb[KC_EMB * 256];  // packed split-bf16 emb weight
__device__ uint4    g_Bw[12 * 1024];       // q,k,v,o x 3 layers (K=64 -> KC=4)

// ---------------- helpers ----------------
__device__ __forceinline__ void split2(float x, float y, unsigned& hi, unsigned& lo) {
    __nv_bfloat162 h = __floats2bfloat162_rn(x, y);
    float rx = x - __low2float(h);
    float ry = y - __high2float(h);
    __nv_bfloat162 l = __floats2bfloat162_rn(rx, ry);
    hi = *reinterpret_cast<unsigned*>(&h);
    lo = *reinterpret_cast<unsigned*>(&l);
}

__device__ __forceinline__ void mma16816(float* c, const unsigned* a,
                                         unsigned b0, unsigned b1) {
    asm volatile(
        "mma.sync.aligned.m16n8k16.row.col.f32.bf16.bf16.f32 "
        "{%0,%1,%2,%3},{%4,%5,%6,%7},{%8,%9},{%0,%1,%2,%3};\n"
        : "+f"(c[0]), "+f"(c[1]), "+f"(c[2]), "+f"(c[3])
        : "r"(a[0]), "r"(a[1]), "r"(a[2]), "r"(a[3]), "r"(b0), "r"(b1));
}

__device__ __forceinline__ float2 h2f2(unsigned w) {
    return __half22float2(*reinterpret_cast<__half2*>(&w));
}

// ---------------- B packing ----------------
__global__ void pack_b_kernel(const float* __restrict__ B, uint4* __restrict__ out,
                              int K, int KC) {
    int idx = blockIdx.x * blockDim.x + threadIdx.x;
    if (idx >= KC * 256) return;
    int lane = idx & 31, nt = (idx >> 5) & 7, kc = idx >> 8;
    int col = nt * 8 + (lane >> 2);
    int kr = kc * 16 + (lane & 3) * 2;
    float f0 = (kr     < K) ? B[(kr    ) * 64 + col] : 0.f;
    float f1 = (kr + 1 < K) ? B[(kr + 1) * 64 + col] : 0.f;
    float f2 = (kr + 8 < K) ? B[(kr + 8) * 64 + col] : 0.f;
    float f3 = (kr + 9 < K) ? B[(kr + 9) * 64 + col] : 0.f;
    unsigned h0, l0, h1, l1;
    split2(f0, f1, h0, l0);
    split2(f2, f3, h1, l1);
    out[idx] = make_uint4(h0, h1, l0, l1);
}

__global__ void pack_w_kernel(const float* __restrict__ Wq, const float* __restrict__ Wk,
                              const float* __restrict__ Wv, const float* __restrict__ Wo,
                              uint4* __restrict__ out) {
    int idx = blockIdx.x * blockDim.x + threadIdx.x;
    if (idx >= 12 * 1024) return;
    int m = idx >> 10;
    int l = m >> 2, w = m & 3;
    const float* B = (w == 0 ? Wq : w == 1 ? Wk : w == 2 ? Wv : Wo) + l * 4096;
    int rest = idx & 1023;
    int lane = rest & 31, nt = (rest >> 5) & 7, kc = rest >> 8;
    int col = nt * 8 + (lane >> 2);
    int kr = kc * 16 + (lane & 3) * 2;
    float f0 = B[(kr    ) * 64 + col];
    float f1 = B[(kr + 1) * 64 + col];
    float f2 = B[(kr + 8) * 64 + col];
    float f3 = B[(kr + 9) * 64 + col];
    unsigned h0, l0, h1, l1;
    split2(f0, f1, h0, l0);
    split2(f2, f3, h1, l1);
    out[idx] = make_uint4(h0, h1, l0, l1);
}

// ------- fused GEMM: main GEMM + (bias|gate) + LN + in-register QKV GEMMs --
// A staged via 4-byte cp.async into double-buffered smem; HW async pipeline.
template <int EPI>
__global__ __launch_bounds__(128)
void gemm_fused_kernel(const float* __restrict__ A, const uint4* __restrict__ Bp,
                       float* __restrict__ O0,
                       const float* __restrict__ bias_gw,
                       const float* __restrict__ gb,
                       const float* __restrict__ res,
                       const float* __restrict__ x0p,
                       const float* __restrict__ lns,
                       const float* __restrict__ lnb,
                       const uint4* __restrict__ Bqkv,
                       float* __restrict__ Oq,
                       int M, int K, int KC) {
    __shared__ float sA[2][64 * 32];
    const int tid = threadIdx.x, warp = tid >> 5, lane = tid & 31;
    const int rowBase = blockIdx.x * 64;
    const int nStages = (KC + 1) >> 1;

    float acc[8][4];
#pragma unroll
    for (int nt = 0; nt < 8; ++nt)
#pragma unroll
        for (int j = 0; j < 4; ++j) acc[nt][j] = 0.f;

    const int cr0 = warp * 16 + (lane >> 2);
    const int cr1 = cr0 + 8;
    const int sw0 = (cr0 & 3) << 3;
    const int sw1 = (cr1 & 3) << 3;

#define PREFETCH(ST, BUF)                                                      \
    do {                                                                       \
        int gc = (ST) * 32 + lane;                                             \
        bool cok = gc < K;                                                     \
        _Pragma("unroll")                                                      \
        for (int i = 0; i < 16; ++i) {                                         \
            int rr = i * 4 + warp;                                             \
            int gr = rowBase + rr;                                             \
            bool ok = (gr < M) && cok;                                         \
            int sz = ok ? 4 : 0;                                               \
            const float* src = ok ? (A + (long)gr * K + gc) : A;               \
            unsigned dst = (unsigned)__cvta_generic_to_shared(                 \
                &sA[BUF][rr * 32 + (lane ^ ((rr & 3) << 3))]);                 \
            asm volatile("cp.async.ca.shared.global [%0], [%1], 4, %2;\n"      \
                         :: "r"(dst), "l"(src), "r"(sz));                      \
        }                                                                      \
        asm volatile("cp.async.commit_group;\n");                              \
    } while (0)

    PREFETCH(0, 0);
    for (int st = 0; st < nStages; ++st) {
        const int buf = st & 1;
        if (st + 1 < nStages) PREFETCH(st + 1, buf ^ 1);
        else asm volatile("cp.async.commit_group;\n");
        asm volatile("cp.async.wait_group 1;\n");
        __syncthreads();
#pragma unroll
        for (int half = 0; half < 2; ++half) {
            int kc = st * 2 + half;
            if (kc < KC) {
                int c0 = half * 16 + (lane & 3) * 2;
                const float* sb = sA[buf];
                float2 fA = *(const float2*)&sb[cr0 * 32 + ((c0    ) ^ sw0)];
                float2 fB = *(const float2*)&sb[cr1 * 32 + ((c0    ) ^ sw1)];
                float2 fC = *(const float2*)&sb[cr0 * 32 + ((c0 + 8) ^ sw0)];
                float2 fD = *(const float2*)&sb[cr1 * 32 + ((c0 + 8) ^ sw1)];
                unsigned ahi[4], alo[4];
                split2(fA.x, fA.y, ahi[0], alo[0]);
                split2(fB.x, fB.y, ahi[1], alo[1]);
                split2(fC.x, fC.y, ahi[2], alo[2]);
                split2(fD.x, fD.y, ahi[3], alo[3]);
                const uint4* bp = Bp + (size_t)kc * 256 + lane;
#pragma unroll
                for (int nt = 0; nt < 8; ++nt) {
                    uint4 b = __ldg(&bp[nt * 32]);
                    mma16816(acc[nt], ahi, b.x, b.y);
                    mma16816(acc[nt], alo, b.x, b.y);
                    mma16816(acc[nt], ahi, b.z, b.w);
                }
            }
        }
        __syncthreads();
    }
#undef PREFETCH

    const int cbase = (lane & 3) * 2;
    const int gr[2] = { rowBase + cr0, rowBase + cr1 };
    float hv[2][8][2];          // row values in A-fragment layout
    float sum[2] = {0.f, 0.f}, sq[2] = {0.f, 0.f};

    if (EPI == 1) {
        // embedding: bias add, store x0, LN -> hv
#pragma unroll
        for (int f = 0; f < 2; ++f)
#pragma unroll
            for (int nt = 0; nt < 8; ++nt) {
                int cc = nt * 8 + cbase;
                float a0 = acc[nt][2 * f]     + bias_gw[cc];
                float a1 = acc[nt][2 * f + 1] + bias_gw[cc + 1];
                hv[f][nt][0] = a0; hv[f][nt][1] = a1;
                sum[f] += a0 + a1;
                sq[f]  += a0 * a0 + a1 * a1;
                if (gr[f] < M)
                    *(float2*)(O0 + (long)gr[f] * 64 + cc) = make_float2(a0, a1);
            }
    } else {
        // EPI 2: gated residual + alpha mix
        const float* gw = bias_gw;
        float rr[2][8][2], zz[2][8][2];
        float s[2] = {0.f, 0.f};
#pragma unroll
        for (int f = 0; f < 2; ++f) {
            bool ok = gr[f] < M;
#pragma unroll
            for (int nt = 0; nt < 8; ++nt) {
                int cc = nt * 8 + cbase;
                float2 rv = ok ? *(const float2*)(res + (long)gr[f] * 64 + cc)
                               : make_float2(0.f, 0.f);
                float2 zv = ok ? *(const float2*)(x0p + (long)gr[f] * 64 + cc)
                               : make_float2(0.f, 0.f);
                rr[f][nt][0] = rv.x; rr[f][nt][1] = rv.y;
                zz[f][nt][0] = zv.x; zz[f][nt][1] = zv.y;
                float o0 = acc[nt][2 * f], o1 = acc[nt][2 * f + 1];
                s[f] += o0 * gw[cc]        + o1 * gw[cc + 1]
                      + rv.x * gw[64 + cc] + rv.y * gw[65 + cc]
                      + (o0 - rv.x) * gw[128 + cc] + (o1 - rv.y) * gw[129 + cc];
            }
        }
#pragma unroll
        for (int o = 1; o <= 2; o <<= 1) {
            s[0] += __shfl_xor_sync(~0u, s[0], o);
            s[1] += __shfl_xor_sync(~0u, s[1], o);
        }
#pragma unroll
        for (int f = 0; f < 2; ++f) {
            float g = 1.f / (1.f + __expf(-(s[f] + gb[0])));
#pragma unroll
            for (int nt = 0; nt < 8; ++nt) {
                float o0 = acc[nt][2 * f], o1 = acc[nt][2 * f + 1];
                float n0 = ALPHA * (g * o0 + (1.f - g) * rr[f][nt][0])
                         + (1.f - ALPHA) * zz[f][nt][0];
                float n1 = ALPHA * (g * o1 + (1.f - g) * rr[f][nt][1])
                         + (1.f - ALPHA) * zz[f][nt][1];
                hv[f][nt][0] = n0; hv[f][nt][1] = n1;
                sum[f] += n0 + n1;
                sq[f]  += n0 * n0 + n1 * n1;
                if (gr[f] < M) {
                    int cc = nt * 8 + cbase;
                    *(float2*)(O0 + (long)gr[f] * 64 + cc) = make_float2(n0, n1);
                }
            }
        }
    }

    if (lns) {
        // LayerNorm in registers (quad reduction over the 4 lanes of a row)
#pragma unroll
        for (int o = 1; o <= 2; o <<= 1) {
            sum[0] += __shfl_xor_sync(~0u, sum[0], o);
            sum[1] += __shfl_xor_sync(~0u, sum[1], o);
            sq[0]  += __shfl_xor_sync(~0u, sq[0],  o);
            sq[1]  += __shfl_xor_sync(~0u, sq[1],  o);
        }
#pragma unroll
        for (int f = 0; f < 2; ++f) {
            float mu = sum[f] * (1.f / 64.f);
            float var = sq[f] * (1.f / 64.f) - mu * mu;
            float rstd = rsqrtf(var + 1e-5f);
#pragma unroll
            for (int nt = 0; nt < 8; ++nt) {
                int cc = nt * 8 + cbase;
                hv[f][nt][0] = (hv[f][nt][0] - mu) * rstd * lns[cc]     + lnb[cc];
                hv[f][nt][1] = (hv[f][nt][1] - mu) * rstd * lns[cc + 1] + lnb[cc + 1];
            }
        }
    }

    if (Bqkv) {
        // in-register QKV GEMMs: hv already sits in mma A-fragment layout
#pragma unroll
        for (int m = 0; m < 3; ++m) {
            float a2[8][4];
#pragma unroll
            for (int nt = 0; nt < 8; ++nt)
#pragma unroll
                for (int j = 0; j < 4; ++j) a2[nt][j] = 0.f;
#pragma unroll
            for (int kc = 0; kc < 4; ++kc) {
                unsigned ahi[4], alo[4];
                split2(hv[0][2*kc][0],   hv[0][2*kc][1],   ahi[0], alo[0]);
                split2(hv[1][2*kc][0],   hv[1][2*kc][1],   ahi[1], alo[1]);
                split2(hv[0][2*kc+1][0], hv[0][2*kc+1][1], ahi[2], alo[2]);
                split2(hv[1][2*kc+1][0], hv[1][2*kc+1][1], ahi[3], alo[3]);
                const uint4* bm = Bqkv + (size_t)m * 1024 + kc * 256 + lane;
#pragma unroll
                for (int nt = 0; nt < 8; ++nt) {
                    uint4 b = __ldg(&bm[nt * 32]);
                    mma16816(a2[nt], ahi, b.x, b.y);
                    mma16816(a2[nt], alo, b.x, b.y);
                    mma16816(a2[nt], ahi, b.z, b.w);
                }
            }
            if (m == 0) {
                // q in fp32
#pragma unroll
                for (int f = 0; f < 2; ++f) {
                    if (gr[f] >= M) continue;
#pragma unroll
                    for (int nt = 0; nt < 8; ++nt) {
                        int cc = nt * 8 + cbase;
                        *(float2*)(Oq + (long)gr[f] * 64 + cc) =
                            make_float2(a2[nt][2 * f], a2[nt][2 * f + 1]);
                    }
                }
            } else {
                // k/v packed half2
                unsigned* O2 = (m == 1) ? g_k2 : g_v2;
#pragma unroll
                for (int f = 0; f < 2; ++f) {
                    if (gr[f] >= M) continue;
#pragma unroll
                    for (int nt = 0; nt < 8; ++nt) {
                        __half2 hh = __floats2half2_rn(a2[nt][2 * f],
                                                       a2[nt][2 * f + 1]);
                        O2[(long)gr[f] * 32 + nt * 4 + (lane & 3)] =
                            *reinterpret_cast<unsigned*>(&hh);
                    }
                }
            }
        }
    }
}

// ---------------- CSR construction ----------------
__global__ void zero_deg_kernel() {
    int i = blockIdx.x * blockDim.x + threadIdx.x;
    if (i < NN) g_deg[i] = 0;
}

__global__ void hist_kernel(const int* __restrict__ ei) {
    int e = blockIdx.x * blockDim.x + threadIdx.x;
    if (e < EE) atomicAdd(&g_deg[ei[EE + e]], 1);
}

__global__ void scan_kernel() {
    __shared__ int ssum[1024];
    const int t = threadIdx.x;
    const int CHUNK = (NN + 1023) / 1024;
    int beg = t * CHUNK;
    int end = beg + CHUNK; if (end > NN) end = NN;
    int s = 0;
    for (int i = beg; i < end; ++i) s += g_deg[i];
    ssum[t] = s;
    __syncthreads();
    for (int d = 1; d < 1024; d <<= 1) {
        int v = (t >= d) ? ssum[t - d] : 0;
        __syncthreads();
        ssum[t] += v;
        __syncthreads();
    }
    int run = (t == 0) ? 0 : ssum[t - 1];
    for (int i = beg; i < end; ++i) {
        g_off[i] = run;
        g_pos[i] = run;
        run += g_deg[i];
    }
    if (t == 1023) g_off[NN] = ssum[1023];
}

__global__ void fill_kernel(const int* __restrict__ ei) {
    int e = blockIdx.x * blockDim.x + threadIdx.x;
    if (e < EE) {
        int d = ei[EE + e];
        int p = atomicAdd(&g_pos[d], 1);
        g_csr[p] = ei[e];
    }
}

// ---------------- fused edge attention: warp per dst, half2 k/v ------------
__global__ __launch_bounds__(256)
void attn_kernel() {
    int warp = (blockIdx.x * blockDim.x + threadIdx.x) >> 5;
    int lane = threadIdx.x & 31;
    if (warp >= NN) return;
    float2 qv = ((const float2*)(g_q + (size_t)warp * 64))[lane];
    qv.x *= 0.25f; qv.y *= 0.25f;      // fold DH^-0.5
    float l = 0.f, lB = 0.f;
    float ax = 0.f, ay = 0.f, bx = 0.f, by = 0.f;
    int beg = g_off[warp], end = g_off[warp + 1];
    int e = beg;
    for (; e + 1 < end; e += 2) {
        int s0 = g_csr[e], s1 = g_csr[e + 1];
        unsigned kw0 = g_k2[(size_t)s0 * 32 + lane];
        unsigned vw0 = g_v2[(size_t)s0 * 32 + lane];
        unsigned kw1 = g_k2[(size_t)s1 * 32 + lane];
        unsigned vw1 = g_v2[(size_t)s1 * 32 + lane];
        float2 k0 = h2f2(kw0), v0 = h2f2(vw0);
        float2 k1 = h2f2(kw1), v1 = h2f2(vw1);
        float d0 = qv.x * k0.x + qv.y * k0.y;
        float d1 = qv.x * k1.x + qv.y * k1.y;
#pragma unroll
        for (int o = 4; o; o >>= 1) {
            d0 += __shfl_xor_sync(~0u, d0, o);
            d1 += __shfl_xor_sync(~0u, d1, o);
        }
        float p0 = __expf(d0), p1 = __expf(d1);
        l  += p0;  ax += p0 * v0.x;  ay += p0 * v0.y;
        lB += p1;  bx += p1 * v1.x;  by += p1 * v1.y;
    }
    if (e < end) {
        int s0 = g_csr[e];
        unsigned kw0 = g_k2[(size_t)s0 * 32 + lane];
        unsigned vw0 = g_v2[(size_t)s0 * 32 + lane];
        float2 k0 = h2f2(kw0), v0 = h2f2(vw0);
        float d0 = qv.x * k0.x + qv.y * k0.y;
#pragma unroll
        for (int o = 4; o; o >>= 1) d0 += __shfl_xor_sync(~0u, d0, o);
        float p0 = __expf(d0);
        l += p0; ax += p0 * v0.x; ay += p0 * v0.y;
    }
    l += lB; ax += bx; ay += by;
    float inv = 1.f / (l + 1e-9f);
    ((float2*)(g_agg + (size_t)warp * 64))[lane] = make_float2(ax * inv, ay * inv);
}

// ---------------- launch ----------------
static cudaStream_t s_aux = 0;
static cudaEvent_t  s_evFork = 0, s_evJoin = 0;

extern "C" void kernel_launch(void* const* d_in, const int* in_sizes, int n_in,
                              void* d_out, int out_size) {
    const float* nodes = (const float*)d_in[0];
    const int*   ei    = (const int*)  d_in[1];
    const float* emb_W = (const float*)d_in[2];
    const float* emb_b = (const float*)d_in[3];
    const float* ln_s  = (const float*)d_in[4];
    const float* ln_b  = (const float*)d_in[5];
    const float* Wq    = (const float*)d_in[6];
    const float* Wk    = (const float*)d_in[7];
    const float* Wv    = (const float*)d_in[8];
    const float* Wo    = (const float*)d_in[9];
    const float* gW    = (const float*)d_in[10];
    const float* gb    = (const float*)d_in[11];
    float* out = (float*)d_out;

    // one-time host-side resources (created on the uncaptured correctness
    // call; reused identically on every call — same launched work each time)
    if (!s_aux) {
        cudaStreamCreateWithFlags(&s_aux, cudaStreamNonBlocking);
        cudaEventCreateWithFlags(&s_evFork, cudaEventDisableTiming);
        cudaEventCreateWithFlags(&s_evJoin, cudaEventDisableTiming);
    }

    float *px0, *px, *pagg, *pq;
    uint4 *pBemb, *pBw;
    cudaGetSymbolAddress((void**)&px0,  g_x0);
    cudaGetSymbolAddress((void**)&px,   g_x);
    cudaGetSymbolAddress((void**)&pagg, g_agg);
    cudaGetSymbolAddress((void**)&pq,   g_q);
    cudaGetSymbolAddress((void**)&pBemb, g_Bemb);
    cudaGetSymbolAddress((void**)&pBw,   g_Bw);

    const int gemmGrid = (NN + 63) / 64;     // 1563
    const int warpGrid = (NN + 7) / 8;

    // ---- fork: CSR build on aux stream, overlapped with pack + emb GEMM ----
    cudaEventRecord(s_evFork, 0);
    cudaStreamWaitEvent(s_aux, s_evFork, 0);
    zero_deg_kernel<<<(NN + 255) / 256, 256, 0, s_aux>>>();
    hist_kernel<<<(EE + 255) / 256, 256, 0, s_aux>>>(ei);
    scan_kernel<<<1, 1024, 0, s_aux>>>();
    fill_kernel<<<(EE + 255) / 256, 256, 0, s_aux>>>(ei);
    cudaEventRecord(s_evJoin, s_aux);

    // ---- main stream: weight packing + fused embedding GEMM ----
    pack_b_kernel<<<(KC_EMB * 256 + 255) / 256, 256>>>(emb_W, pBemb, F_IN, KC_EMB);
    pack_w_kernel<<<(12 * 1024 + 255) / 256, 256>>>(Wq, Wk, Wv, Wo, pBw);
    gemm_fused_kernel<1><<<gemmGrid, 128>>>(
        nodes, pBemb, px0, emb_b, nullptr, nullptr, nullptr,
        ln_s, ln_b, pBw, pq, NN, F_IN, KC_EMB);

    // ---- join: attn needs CSR (aux) and q/k/v (main) ----
    cudaStreamWaitEvent(0, s_evJoin, 0);

    for (int l = 0; l < DEPTH; ++l) {
        attn_kernel<<<warpGrid, 256>>>();   // q,k,v -> agg
        const float* res = (l == 0) ? px0 : px;
        float* dst = (l == DEPTH - 1) ? out : px;
        const float* nls = (l == DEPTH - 1) ? nullptr : ln_s + (l + 1) * 64;
        const float* nlb = (l == DEPTH - 1) ? nullptr : ln_b + (l + 1) * 64;
        const uint4* bqkv = (l == DEPTH - 1) ? nullptr
                                             : pBw + (size_t)(l + 1) * 4 * 1024;
        // Wo GEMM + gate + alpha mix + next LN + next QKV, all fused
        gemm_fused_kernel<2><<<gemmGrid, 128>>>(
            pagg, pBw + (size_t)(l * 4 + 3) * 1024, dst,
            gW + l * 192, gb + l, res, px0, nls, nlb,
            bqkv, pq, NN, 64, 4);
    }
}

// round 17
// speedup vs baseline: 2.1885x; 1.0468x over previous
#include <cuda_runtime.h>
#include <cuda_bf16.h>
#include <cuda_fp16.h>
#include <math.h>

#define NN 100000
#define EE 1600000
#define F_IN 1433
#define DD 64
#define DEPTH 3
#define ALPHA 0.9f
#define KC_EMB 90   // ceil(1433/16)

// ---------------- scratch (static device globals) ----------------
__device__ float    g_x0[NN * DD];
__device__ float    g_x [NN * DD];
__device__ float    g_agg[NN * DD];
__device__ float    g_q [NN * DD];
__device__ unsigned g_kv2[NN * 64];  // interleaved per-lane {k half2, v half2}
__device__ int      g_deg[NN];
__device__ int      g_off[NN + 1];
__device__ int      g_pos[NN];
__device__ int      g_csr[EE];
__device__ uint4    g_Bemb[KC_EMB * 256];  // packed split-bf16 emb weight
__device__ uint4    g_Bw[12 * 1024];       // q,k,v,o x 3 layers (K=64 -> KC=4)

// ---------------- helpers ----------------
__device__ __forceinline__ void split2(float x, float y, unsigned& hi, unsigned& lo) {
    __nv_bfloat162 h = __floats2bfloat162_rn(x, y);
    float rx = x - __low2float(h);
    float ry = y - __high2float(h);
    __nv_bfloat162 l = __floats2bfloat162_rn(rx, ry);
    hi = *reinterpret_cast<unsigned*>(&h);
    lo = *reinterpret_cast<unsigned*>(&l);
}

__device__ __forceinline__ void mma16816(float* c, const unsigned* a,
                                         unsigned b0, unsigned b1) {
    asm volatile(
        "mma.sync.aligned.m16n8k16.row.col.f32.bf16.bf16.f32 "
        "{%0,%1,%2,%3},{%4,%5,%6,%7},{%8,%9},{%0,%1,%2,%3};\n"
        : "+f"(c[0]), "+f"(c[1]), "+f"(c[2]), "+f"(c[3])
        : "r"(a[0]), "r"(a[1]), "r"(a[2]), "r"(a[3]), "r"(b0), "r"(b1));
}

__device__ __forceinline__ float2 h2f2(unsigned w) {
    return __half22float2(*reinterpret_cast<__half2*>(&w));
}

// ---------------- B packing ----------------
__global__ void pack_b_kernel(const float* __restrict__ B, uint4* __restrict__ out,
                              int K, int KC) {
    int idx = blockIdx.x * blockDim.x + threadIdx.x;
    if (idx >= KC * 256) return;
    int lane = idx & 31, nt = (idx >> 5) & 7, kc = idx >> 8;
    int col = nt * 8 + (lane >> 2);
    int kr = kc * 16 + (lane & 3) * 2;
    float f0 = (kr     < K) ? B[(kr    ) * 64 + col] : 0.f;
    float f1 = (kr + 1 < K) ? B[(kr + 1) * 64 + col] : 0.f;
    float f2 = (kr + 8 < K) ? B[(kr + 8) * 64 + col] : 0.f;
    float f3 = (kr + 9 < K) ? B[(kr + 9) * 64 + col] : 0.f;
    unsigned h0, l0, h1, l1;
    split2(f0, f1, h0, l0);
    split2(f2, f3, h1, l1);
    out[idx] = make_uint4(h0, h1, l0, l1);
}

__global__ void pack_w_kernel(const float* __restrict__ Wq, const float* __restrict__ Wk,
                              const float* __restrict__ Wv, const float* __restrict__ Wo,
                              uint4* __restrict__ out) {
    int idx = blockIdx.x * blockDim.x + threadIdx.x;
    if (idx >= 12 * 1024) return;
    int m = idx >> 10;
    int l = m >> 2, w = m & 3;
    const float* B = (w == 0 ? Wq : w == 1 ? Wk : w == 2 ? Wv : Wo) + l * 4096;
    int rest = idx & 1023;
    int lane = rest & 31, nt = (rest >> 5) & 7, kc = rest >> 8;
    int col = nt * 8 + (lane >> 2);
    int kr = kc * 16 + (lane & 3) * 2;
    float f0 = B[(kr    ) * 64 + col];
    float f1 = B[(kr + 1) * 64 + col];
    float f2 = B[(kr + 8) * 64 + col];
    float f3 = B[(kr + 9) * 64 + col];
    unsigned h0, l0, h1, l1;
    split2(f0, f1, h0, l0);
    split2(f2, f3, h1, l1);
    out[idx] = make_uint4(h0, h1, l0, l1);
}

// ------- fused GEMM: main GEMM + (bias|gate) + LN + in-register QKV GEMMs --
// A staged via 4-byte cp.async into double-buffered smem; HW async pipeline.
template <int EPI>
__global__ __launch_bounds__(128)
void gemm_fused_kernel(const float* __restrict__ A, const uint4* __restrict__ Bp,
                       float* __restrict__ O0,
                       const float* __restrict__ bias_gw,
                       const float* __restrict__ gb,
                       const float* __restrict__ res,
                       const float* __restrict__ x0p,
                       const float* __restrict__ lns,
                       const float* __restrict__ lnb,
                       const uint4* __restrict__ Bqkv,
                       float* __restrict__ Oq,
                       int M, int K, int KC) {
    __shared__ float sA[2][64 * 32];
    const int tid = threadIdx.x, warp = tid >> 5, lane = tid & 31;
    const int rowBase = blockIdx.x * 64;
    const int nStages = (KC + 1) >> 1;

    float acc[8][4];
#pragma unroll
    for (int nt = 0; nt < 8; ++nt)
#pragma unroll
        for (int j = 0; j < 4; ++j) acc[nt][j] = 0.f;

    const int cr0 = warp * 16 + (lane >> 2);
    const int cr1 = cr0 + 8;
    const int sw0 = (cr0 & 3) << 3;
    const int sw1 = (cr1 & 3) << 3;

#define PREFETCH(ST, BUF)                                                      \
    do {                                                                       \
        int gc = (ST) * 32 + lane;                                             \
        bool cok = gc < K;                                                     \
        _Pragma("unroll")                                                      \
        for (int i = 0; i < 16; ++i) {                                         \
            int rr = i * 4 + warp;                                             \
            int gr = rowBase + rr;                                             \
            bool ok = (gr < M) && cok;                                         \
            int sz = ok ? 4 : 0;                                               \
            const float* src = ok ? (A + (long)gr * K + gc) : A;               \
            unsigned dst = (unsigned)__cvta_generic_to_shared(                 \
                &sA[BUF][rr * 32 + (lane ^ ((rr & 3) << 3))]);                 \
            asm volatile("cp.async.ca.shared.global [%0], [%1], 4, %2;\n"      \
                         :: "r"(dst), "l"(src), "r"(sz));                      \
        }                                                                      \
        asm volatile("cp.async.commit_group;\n");                              \
    } while (0)

    PREFETCH(0, 0);
    for (int st = 0; st < nStages; ++st) {
        const int buf = st & 1;
        if (st + 1 < nStages) PREFETCH(st + 1, buf ^ 1);
        else asm volatile("cp.async.commit_group;\n");
        asm volatile("cp.async.wait_group 1;\n");
        __syncthreads();
#pragma unroll
        for (int half = 0; half < 2; ++half) {
            int kc = st * 2 + half;
            if (kc < KC) {
                int c0 = half * 16 + (lane & 3) * 2;
                const float* sb = sA[buf];
                float2 fA = *(const float2*)&sb[cr0 * 32 + ((c0    ) ^ sw0)];
                float2 fB = *(const float2*)&sb[cr1 * 32 + ((c0    ) ^ sw1)];
                float2 fC = *(const float2*)&sb[cr0 * 32 + ((c0 + 8) ^ sw0)];
                float2 fD = *(const float2*)&sb[cr1 * 32 + ((c0 + 8) ^ sw1)];
                unsigned ahi[4], alo[4];
                split2(fA.x, fA.y, ahi[0], alo[0]);
                split2(fB.x, fB.y, ahi[1], alo[1]);
                split2(fC.x, fC.y, ahi[2], alo[2]);
                split2(fD.x, fD.y, ahi[3], alo[3]);
                const uint4* bp = Bp + (size_t)kc * 256 + lane;
#pragma unroll
                for (int nt = 0; nt < 8; ++nt) {
                    uint4 b = __ldg(&bp[nt * 32]);
                    mma16816(acc[nt], ahi, b.x, b.y);
                    mma16816(acc[nt], alo, b.x, b.y);
                    mma16816(acc[nt], ahi, b.z, b.w);
                }
            }
        }
        __syncthreads();
    }
#undef PREFETCH

    const int cbase = (lane & 3) * 2;
    const int gr[2] = { rowBase + cr0, rowBase + cr1 };
    float hv[2][8][2];          // row values in A-fragment layout
    float sum[2] = {0.f, 0.f}, sq[2] = {0.f, 0.f};

    if (EPI == 1) {
        // embedding: bias add, store x0, LN -> hv
#pragma unroll
        for (int f = 0; f < 2; ++f)
#pragma unroll
            for (int nt = 0; nt < 8; ++nt) {
                int cc = nt * 8 + cbase;
                float a0 = acc[nt][2 * f]     + bias_gw[cc];
                float a1 = acc[nt][2 * f + 1] + bias_gw[cc + 1];
                hv[f][nt][0] = a0; hv[f][nt][1] = a1;
                sum[f] += a0 + a1;
                sq[f]  += a0 * a0 + a1 * a1;
                if (gr[f] < M)
                    *(float2*)(O0 + (long)gr[f] * 64 + cc) = make_float2(a0, a1);
            }
    } else {
        // EPI 2: gated residual + alpha mix
        const float* gw = bias_gw;
        float rr[2][8][2], zz[2][8][2];
        float s[2] = {0.f, 0.f};
#pragma unroll
        for (int f = 0; f < 2; ++f) {
            bool ok = gr[f] < M;
#pragma unroll
            for (int nt = 0; nt < 8; ++nt) {
                int cc = nt * 8 + cbase;
                float2 rv = ok ? *(const float2*)(res + (long)gr[f] * 64 + cc)
                               : make_float2(0.f, 0.f);
                float2 zv = ok ? *(const float2*)(x0p + (long)gr[f] * 64 + cc)
                               : make_float2(0.f, 0.f);
                rr[f][nt][0] = rv.x; rr[f][nt][1] = rv.y;
                zz[f][nt][0] = zv.x; zz[f][nt][1] = zv.y;
                float o0 = acc[nt][2 * f], o1 = acc[nt][2 * f + 1];
                s[f] += o0 * gw[cc]        + o1 * gw[cc + 1]
                      + rv.x * gw[64 + cc] + rv.y * gw[65 + cc]
                      + (o0 - rv.x) * gw[128 + cc] + (o1 - rv.y) * gw[129 + cc];
            }
        }
#pragma unroll
        for (int o = 1; o <= 2; o <<= 1) {
            s[0] += __shfl_xor_sync(~0u, s[0], o);
            s[1] += __shfl_xor_sync(~0u, s[1], o);
        }
#pragma unroll
        for (int f = 0; f < 2; ++f) {
            float g = 1.f / (1.f + __expf(-(s[f] + gb[0])));
#pragma unroll
            for (int nt = 0; nt < 8; ++nt) {
                float o0 = acc[nt][2 * f], o1 = acc[nt][2 * f + 1];
                float n0 = ALPHA * (g * o0 + (1.f - g) * rr[f][nt][0])
                         + (1.f - ALPHA) * zz[f][nt][0];
                float n1 = ALPHA * (g * o1 + (1.f - g) * rr[f][nt][1])
                         + (1.f - ALPHA) * zz[f][nt][1];
                hv[f][nt][0] = n0; hv[f][nt][1] = n1;
                sum[f] += n0 + n1;
                sq[f]  += n0 * n0 + n1 * n1;
                if (gr[f] < M) {
                    int cc = nt * 8 + cbase;
                    *(float2*)(O0 + (long)gr[f] * 64 + cc) = make_float2(n0, n1);
                }
            }
        }
    }

    if (lns) {
        // LayerNorm in registers (quad reduction over the 4 lanes of a row)
#pragma unroll
        for (int o = 1; o <= 2; o <<= 1) {
            sum[0] += __shfl_xor_sync(~0u, sum[0], o);
            sum[1] += __shfl_xor_sync(~0u, sum[1], o);
            sq[0]  += __shfl_xor_sync(~0u, sq[0],  o);
            sq[1]  += __shfl_xor_sync(~0u, sq[1],  o);
        }
#pragma unroll
        for (int f = 0; f < 2; ++f) {
            float mu = sum[f] * (1.f / 64.f);
            float var = sq[f] * (1.f / 64.f) - mu * mu;
            float rstd = rsqrtf(var + 1e-5f);
#pragma unroll
            for (int nt = 0; nt < 8; ++nt) {
                int cc = nt * 8 + cbase;
                hv[f][nt][0] = (hv[f][nt][0] - mu) * rstd * lns[cc]     + lnb[cc];
                hv[f][nt][1] = (hv[f][nt][1] - mu) * rstd * lns[cc + 1] + lnb[cc + 1];
            }
        }
    }

    if (Bqkv) {
        // in-register QKV GEMMs: hv already sits in mma A-fragment layout
#pragma unroll
        for (int m = 0; m < 3; ++m) {
            float a2[8][4];
#pragma unroll
            for (int nt = 0; nt < 8; ++nt)
#pragma unroll
                for (int j = 0; j < 4; ++j) a2[nt][j] = 0.f;
#pragma unroll
            for (int kc = 0; kc < 4; ++kc) {
                unsigned ahi[4], alo[4];
                split2(hv[0][2*kc][0],   hv[0][2*kc][1],   ahi[0], alo[0]);
                split2(hv[1][2*kc][0],   hv[1][2*kc][1],   ahi[1], alo[1]);
                split2(hv[0][2*kc+1][0], hv[0][2*kc+1][1], ahi[2], alo[2]);
                split2(hv[1][2*kc+1][0], hv[1][2*kc+1][1], ahi[3], alo[3]);
                const uint4* bm = Bqkv + (size_t)m * 1024 + kc * 256 + lane;
#pragma unroll
                for (int nt = 0; nt < 8; ++nt) {
                    uint4 b = __ldg(&bm[nt * 32]);
                    mma16816(a2[nt], ahi, b.x, b.y);
                    mma16816(a2[nt], alo, b.x, b.y);
                    mma16816(a2[nt], ahi, b.z, b.w);
                }
            }
            if (m == 0) {
                // q in fp32
#pragma unroll
                for (int f = 0; f < 2; ++f) {
                    if (gr[f] >= M) continue;
#pragma unroll
                    for (int nt = 0; nt < 8; ++nt) {
                        int cc = nt * 8 + cbase;
                        *(float2*)(Oq + (long)gr[f] * 64 + cc) =
                            make_float2(a2[nt][2 * f], a2[nt][2 * f + 1]);
                    }
                }
            } else {
                // k (m==1) at slot 2*idx, v (m==2) at slot 2*idx+1 (interleaved)
#pragma unroll
                for (int f = 0; f < 2; ++f) {
                    if (gr[f] >= M) continue;
#pragma unroll
                    for (int nt = 0; nt < 8; ++nt) {
                        __half2 hh = __floats2half2_rn(a2[nt][2 * f],
                                                       a2[nt][2 * f + 1]);
                        int slot = (nt * 4 + (lane & 3)) * 2 + (m - 1);
                        g_kv2[(long)gr[f] * 64 + slot] =
                            *reinterpret_cast<unsigned*>(&hh);
                    }
                }
            }
        }
    }
}

// ---------------- CSR construction ----------------
__global__ void zero_deg_kernel() {
    int i = blockIdx.x * blockDim.x + threadIdx.x;
    if (i < NN) g_deg[i] = 0;
}

__global__ void hist_kernel(const int* __restrict__ ei) {
    int e = blockIdx.x * blockDim.x + threadIdx.x;
    if (e < EE) atomicAdd(&g_deg[ei[EE + e]], 1);
}

__global__ void scan_kernel() {
    __shared__ int ssum[1024];
    const int t = threadIdx.x;
    const int CHUNK = (NN + 1023) / 1024;
    int beg = t * CHUNK;
    int end = beg + CHUNK; if (end > NN) end = NN;
    int s = 0;
    for (int i = beg; i < end; ++i) s += g_deg[i];
    ssum[t] = s;
    __syncthreads();
    for (int d = 1; d < 1024; d <<= 1) {
        int v = (t >= d) ? ssum[t - d] : 0;
        __syncthreads();
        ssum[t] += v;
        __syncthreads();
    }
    int run = (t == 0) ? 0 : ssum[t - 1];
    for (int i = beg; i < end; ++i) {
        g_off[i] = run;
        g_pos[i] = run;
        run += g_deg[i];
    }
    if (t == 1023) g_off[NN] = ssum[1023];
}

__global__ void fill_kernel(const int* __restrict__ ei) {
    int e = blockIdx.x * blockDim.x + threadIdx.x;
    if (e < EE) {
        int d = ei[EE + e];
        int p = atomicAdd(&g_pos[d], 1);
        g_csr[p] = ei[e];
    }
}

// ---- fused edge attention: warp per dst, interleaved kv, 1 LDG.64/edge ----
__global__ __launch_bounds__(256)
void attn_kernel() {
    int warp = (blockIdx.x * blockDim.x + threadIdx.x) >> 5;
    int lane = threadIdx.x & 31;
    if (warp >= NN) return;
    float2 qv = ((const float2*)(g_q + (size_t)warp * 64))[lane];
    qv.x *= 0.25f; qv.y *= 0.25f;      // fold DH^-0.5
    float l = 0.f, lB = 0.f;
    float ax = 0.f, ay = 0.f, bx = 0.f, by = 0.f;
    int beg = g_off[warp], end = g_off[warp + 1];
    int e = beg;
    for (; e + 1 < end; e += 2) {
        int s0 = g_csr[e], s1 = g_csr[e + 1];
        uint2 w0 = ((const uint2*)(g_kv2 + (size_t)s0 * 64))[lane];
        uint2 w1 = ((const uint2*)(g_kv2 + (size_t)s1 * 64))[lane];
        float2 k0 = h2f2(w0.x), v0 = h2f2(w0.y);
        float2 k1 = h2f2(w1.x), v1 = h2f2(w1.y);
        float d0 = qv.x * k0.x + qv.y * k0.y;
        float d1 = qv.x * k1.x + qv.y * k1.y;
#pragma unroll
        for (int o = 4; o; o >>= 1) {
            d0 += __shfl_xor_sync(~0u, d0, o);
            d1 += __shfl_xor_sync(~0u, d1, o);
        }
        float p0 = __expf(d0), p1 = __expf(d1);
        l  += p0;  ax += p0 * v0.x;  ay += p0 * v0.y;
        lB += p1;  bx += p1 * v1.x;  by += p1 * v1.y;
    }
    if (e < end) {
        int s0 = g_csr[e];
        uint2 w0 = ((const uint2*)(g_kv2 + (size_t)s0 * 64))[lane];
        float2 k0 = h2f2(w0.x), v0 = h2f2(w0.y);
        float d0 = qv.x * k0.x + qv.y * k0.y;
#pragma unroll
        for (int o = 4; o; o >>= 1) d0 += __shfl_xor_sync(~0u, d0, o);
        float p0 = __expf(d0);
        l += p0; ax += p0 * v0.x; ay += p0 * v0.y;
    }
    l += lB; ax += bx; ay += by;
    float inv = 1.f / (l + 1e-9f);
    ((float2*)(g_agg + (size_t)warp * 64))[lane] = make_float2(ax * inv, ay * inv);
}

// ---------------- launch ----------------
static cudaStream_t s_aux = 0;
static cudaEvent_t  s_evFork = 0, s_evJoin = 0;

extern "C" void kernel_launch(void* const* d_in, const int* in_sizes, int n_in,
                              void* d_out, int out_size) {
    const float* nodes = (const float*)d_in[0];
    const int*   ei    = (const int*)  d_in[1];
    const float* emb_W = (const float*)d_in[2];
    const float* emb_b = (const float*)d_in[3];
    const float* ln_s  = (const float*)d_in[4];
    const float* ln_b  = (const float*)d_in[5];
    const float* Wq    = (const float*)d_in[6];
    const float* Wk    = (const float*)d_in[7];
    const float* Wv    = (const float*)d_in[8];
    const float* Wo    = (const float*)d_in[9];
    const float* gW    = (const float*)d_in[10];
    const float* gb    = (const float*)d_in[11];
    float* out = (float*)d_out;

    if (!s_aux) {
        cudaStreamCreateWithFlags(&s_aux, cudaStreamNonBlocking);
        cudaEventCreateWithFlags(&s_evFork, cudaEventDisableTiming);
        cudaEventCreateWithFlags(&s_evJoin, cudaEventDisableTiming);
    }

    float *px0, *px, *pagg, *pq;
    uint4 *pBemb, *pBw;
    cudaGetSymbolAddress((void**)&px0,  g_x0);
    cudaGetSymbolAddress((void**)&px,   g_x);
    cudaGetSymbolAddress((void**)&pagg, g_agg);
    cudaGetSymbolAddress((void**)&pq,   g_q);
    cudaGetSymbolAddress((void**)&pBemb, g_Bemb);
    cudaGetSymbolAddress((void**)&pBw,   g_Bw);

    const int gemmGrid = (NN + 63) / 64;     // 1563
    const int warpGrid = (NN + 7) / 8;

    // ---- fork: CSR build on aux stream, overlapped with pack + emb GEMM ----
    cudaEventRecord(s_evFork, 0);
    cudaStreamWaitEvent(s_aux, s_evFork, 0);
    zero_deg_kernel<<<(NN + 255) / 256, 256, 0, s_aux>>>();
    hist_kernel<<<(EE + 255) / 256, 256, 0, s_aux>>>(ei);
    scan_kernel<<<1, 1024, 0, s_aux>>>();
    fill_kernel<<<(EE + 255) / 256, 256, 0, s_aux>>>(ei);
    cudaEventRecord(s_evJoin, s_aux);

    // ---- main stream: weight packing + fused embedding GEMM ----
    pack_b_kernel<<<(KC_EMB * 256 + 255) / 256, 256>>>(emb_W, pBemb, F_IN, KC_EMB);
    pack_w_kernel<<<(12 * 1024 + 255) / 256, 256>>>(Wq, Wk, Wv, Wo, pBw);
    gemm_fused_kernel<1><<<gemmGrid, 128>>>(
        nodes, pBemb, px0, emb_b, nullptr, nullptr, nullptr,
        ln_s, ln_b, pBw, pq, NN, F_IN, KC_EMB);

    // ---- join: attn needs CSR (aux) and q/k/v (main) ----
    cudaStreamWaitEvent(0, s_evJoin, 0);

    for (int l = 0; l < DEPTH; ++l) {
        attn_kernel<<<warpGrid, 256>>>();   // q,kv -> agg
        const float* res = (l == 0) ? px0 : px;
        float* dst = (l == DEPTH - 1) ? out : px;
        const float* nls = (l == DEPTH - 1) ? nullptr : ln_s + (l + 1) * 64;
        const float* nlb = (l == DEPTH - 1) ? nullptr : ln_b + (l + 1) * 64;
        const uint4* bqkv = (l == DEPTH - 1) ? nullptr
                                             : pBw + (size_t)(l + 1) * 4 * 1024;
        // Wo GEMM + gate + alpha mix + next LN + next QKV, all fused
        gemm_fused_kernel<2><<<gemmGrid, 128>>>(
            pagg, pBw + (size_t)(l * 4 + 3) * 1024, dst,
            gW + l * 192, gb + l, res, px0, nls, nlb,
            bqkv, pq, NN, 64, 4);
    }
}